// round 4
// baseline (speedup 1.0000x reference)
#include <cuda_runtime.h>
#include <cstdint>

// Word2DM fused single kernel.
// sim_r = ||Bt^T X_r||_F^2 = <G, H_r> with G = Bt Bt^T, H_r = X_r X_r^T (both symmetric).
// loss_b = softplus(-sim_ctx) + sum_k softplus(sim_negk);  out = mean_b loss_b.

#define NDIM    20
#define ROWLEN  400
#define NMATS   11            // 1 context + 10 negatives
#define NPAIRS  210           // 20*21/2 symmetric pairs
#define THREADS 128
#define BMAX    32768

__device__ float        g_partials[BMAX];
__device__ unsigned int g_ctr;      // zero-initialized; modulo pattern is replay-safe

typedef unsigned long long ull;

static __device__ __forceinline__ ull ffma2(ull a, ull b, ull c) {
    ull d;
    asm("fma.rn.f32x2 %0, %1, %2, %3;" : "=l"(d) : "l"(a), "l"(b), "l"(c));
    return d;
}
static __device__ __forceinline__ void unpack2(ull v, float& lo, float& hi) {
    asm("mov.b64 {%0, %1}, %2;" : "=f"(lo), "=f"(hi) : "l"(v));
}
static __device__ __forceinline__ uint32_t smem_u32(const void* p) {
    uint32_t a;
    asm("{ .reg .u64 t; cvta.to.shared.u64 t, %1; cvt.u32.u64 %0, t; }" : "=r"(a) : "l"(p));
    return a;
}
static __device__ __forceinline__ void mbar_init(uint32_t mbar, uint32_t cnt) {
    asm volatile("mbarrier.init.shared.b64 [%0], %1;" :: "r"(mbar), "r"(cnt) : "memory");
}
static __device__ __forceinline__ void mbar_expect_tx(uint32_t mbar, uint32_t bytes) {
    asm volatile("mbarrier.arrive.expect_tx.shared.b64 _, [%0], %1;" :: "r"(mbar), "r"(bytes) : "memory");
}
static __device__ __forceinline__ void mbar_wait0(uint32_t mbar) {
    asm volatile(
        "{\n\t.reg .pred P;\n"
        "W_%=:\n\t"
        "mbarrier.try_wait.parity.shared.b64 P, [%0], 0;\n\t"
        "@!P bra W_%=;\n\t}"
        :: "r"(mbar) : "memory");
}
static __device__ __forceinline__ void bulk_cp(uint32_t dst, const void* src, uint32_t bytes, uint32_t mbar) {
    asm volatile(
        "cp.async.bulk.shared::cta.global.mbarrier::complete_tx::bytes [%0], [%1], %2, [%3];"
        :: "r"(dst), "l"(src), "r"(bytes), "r"(mbar) : "memory");
}

static __device__ __forceinline__ float softplusf(float y) {
    return fmaxf(y, 0.0f) + log1pf(expf(-fabsf(y)));
}

// packed dot of two 20-float rows (16B-aligned), two chains
static __device__ __forceinline__ float dot20(const float* a, const float* b) {
    const ulonglong2* A = (const ulonglong2*)a;
    const ulonglong2* B = (const ulonglong2*)b;
    ull p0 = 0, p1 = 0;
    #pragma unroll
    for (int q = 0; q < 5; q++) {
        ulonglong2 x = A[q], y = B[q];
        p0 = ffma2(x.x, y.x, p0);
        p1 = ffma2(x.y, y.y, p1);
    }
    float a0, a1, b0, b1;
    unpack2(p0, a0, a1);
    unpack2(p1, b0, b1);
    return (a0 + a1) + (b0 + b1);
}

__global__ __launch_bounds__(THREADS)
void w2dm_fused(const float* __restrict__ Wt,
                const float* __restrict__ Wc,
                const int*   __restrict__ tidx,
                const int*   __restrict__ cidx,
                const int*   __restrict__ nidx,
                int kneg, float* __restrict__ out, int B)
{
    __shared__ __align__(16) float s_all[(1 + NMATS) * ROWLEN];  // [Bt | Bc | Bn0..Bn9]
    __shared__ __align__(16) float s_g[ROWLEN];                  // weighted G, upper used
    __shared__ __align__(8)  unsigned long long s_mbar[2];       // [0]=Bt, [1]=rest
    __shared__ int   s_idx[1 + NMATS];
    __shared__ float s_sims[NMATS];
    __shared__ float s_term[NMATS];
    __shared__ unsigned s_last;

    const int b = blockIdx.x;
    const int t = threadIdx.x;
    const uint32_t mb0 = smem_u32(&s_mbar[0]);
    const uint32_t mb1 = smem_u32(&s_mbar[1]);

    if (t < 1 + NMATS) {
        int v;
        if (t == 0)      v = tidx[b];
        else if (t == 1) v = cidx[b];
        else             v = nidx[b * kneg + (t - 2)];
        s_idx[t] = v;
    }
    if (t < NMATS) s_sims[t] = 0.0f;
    if (t == 0) { mbar_init(mb0, 1); mbar_init(mb1, 1); }
    __syncthreads();

    // one thread DMAs all 12 rows (1600 B each) into smem
    if (t == 0) {
        mbar_expect_tx(mb0, ROWLEN * 4);
        bulk_cp(smem_u32(s_all), Wt + (size_t)s_idx[0] * ROWLEN, ROWLEN * 4, mb0);
        mbar_expect_tx(mb1, NMATS * ROWLEN * 4);
        #pragma unroll
        for (int r = 1; r <= NMATS; r++)
            bulk_cp(smem_u32(s_all + r * ROWLEN),
                    Wc + (size_t)s_idx[r] * ROWLEN, ROWLEN * 4, mb1);
    }

    // ── Phase A: weighted Gram of Bt (overlaps context DMA) ──
    mbar_wait0(mb0);
    for (int p = t; p < NPAIRS; p += THREADS) {
        int i = 0, rem = p;
        while (rem >= NDIM - i) { rem -= NDIM - i; i++; }
        int j = i + rem;
        float d = dot20(s_all + i * NDIM, s_all + j * NDIM);
        s_g[i * NDIM + j] = (i == j) ? d : 2.0f * d;
    }
    __syncthreads();          // s_g visible
    mbar_wait0(mb1);          // context/neg rows ready

    // ── Phase B: 110 strips = (mat 1..11) x (row-pair ti 0..9) ──
    if (t < NMATS * (NDIM / 2)) {
        const int ti  = t / NMATS;          // 0..9  (warp-neighbors share ti → similar trip counts)
        const int mat = t % NMATS + 1;      // 1..11
        const int i0 = 2 * ti, i1 = 2 * ti + 1;
        const float* X = s_all + mat * ROWLEN;

        // i-rows register-resident
        ull a0r[10], a1r[10];
        #pragma unroll
        for (int q = 0; q < 5; q++) {
            ulonglong2 v0 = ((const ulonglong2*)(X + i0 * NDIM))[q];
            ulonglong2 v1 = ((const ulonglong2*)(X + i1 * NDIM))[q];
            a0r[2*q] = v0.x; a0r[2*q+1] = v0.y;
            a1r[2*q] = v1.x; a1r[2*q+1] = v1.y;
        }

        float acc = 0.0f;
        for (int j = i0; j < NDIM; j++) {
            const ulonglong2* J = (const ulonglong2*)(X + j * NDIM);
            ull p0a = 0, p0b = 0, p1a = 0, p1b = 0;
            #pragma unroll
            for (int q = 0; q < 5; q++) {
                ulonglong2 y = J[q];
                p0a = ffma2(a0r[2*q],   y.x, p0a);
                p0b = ffma2(a0r[2*q+1], y.y, p0b);
                p1a = ffma2(a1r[2*q],   y.x, p1a);
                p1b = ffma2(a1r[2*q+1], y.y, p1b);
            }
            float x0, x1, x2, x3;
            unpack2(p0a, x0, x1); unpack2(p0b, x2, x3);
            float d0 = (x0 + x1) + (x2 + x3);
            unpack2(p1a, x0, x1); unpack2(p1b, x2, x3);
            float d1 = (x0 + x1) + (x2 + x3);

            acc = fmaf(s_g[i0 * NDIM + j], d0, acc);
            if (j > i0)                       // j >= i1
                acc = fmaf(s_g[i1 * NDIM + j], d1, acc);
        }
        atomicAdd(&s_sims[mat - 1], acc);
    }
    __syncthreads();

    if (t < NMATS) {
        float s = s_sims[t];
        s_term[t] = (t == 0) ? softplusf(-s) : softplusf(s);
    }
    __syncthreads();

    if (t == 0) {
        float loss = 0.0f;
        #pragma unroll
        for (int j = 0; j < NMATS; j++) loss += s_term[j];
        g_partials[b] = loss;
        __threadfence();
        unsigned old = atomicAdd(&g_ctr, 1u);
        s_last = (old % (unsigned)gridDim.x == (unsigned)gridDim.x - 1u) ? 1u : 0u;
    }
    __syncthreads();

    // ── last arriving block reduces (fixed-order float4 sweep) ──
    if (s_last) {
        __shared__ float s_red[THREADS];
        float acc = 0.0f;
        const int n4 = B >> 2;
        const float4* p = (const float4*)g_partials;
        for (int i = t; i < n4; i += THREADS) {
            float4 v = p[i];
            acc += (v.x + v.y) + (v.z + v.w);
        }
        s_red[t] = acc;
        __syncthreads();
        #pragma unroll
        for (int w = THREADS / 2; w > 0; w >>= 1) {
            if (t < w) s_red[t] += s_red[t + w];
            __syncthreads();
        }
        if (t == 0) out[0] = s_red[0] / (float)B;
    }
}

extern "C" void kernel_launch(void* const* d_in, const int* in_sizes, int n_in,
                              void* d_out, int out_size)
{
    const float* Wt   = (const float*)d_in[0];
    const float* Wc   = (const float*)d_in[1];
    const int*   tidx = (const int*)d_in[2];
    const int*   cidx = (const int*)d_in[3];
    const int*   nidx = (const int*)d_in[4];

    int B = in_sizes[2];
    if (B > BMAX) B = BMAX;
    int kneg = in_sizes[4] / (B > 0 ? B : 1);

    w2dm_fused<<<B, THREADS>>>(Wt, Wc, tidx, cidx, nidx, kneg, (float*)d_out, B);
}

// round 5
// speedup vs baseline: 1.5401x; 1.5401x over previous
#include <cuda_runtime.h>
#include <cstdint>

// Word2DM via Gram features:
//   sim(b,r) = ||Bt^T X||_F^2 = <Bt Bt^T, X X^T>  (row-Gram matrices, 20x20)
// K1: Gram features (bf16, full 400) for ALL vocab words of W_context.
// K2: per sample: target Gram on the fly + 11 dots vs gathered features -> loss.
// K3: fixed-order mean.

#define NDIM      20
#define ROWLEN    400
#define NMATS     11
#define BMAX      32768
#define VOCAB_MAX 100000

__device__ float    g_partials[BMAX];
__device__ uint16_t g_hfeat[(size_t)VOCAB_MAX * ROWLEN];   // bf16 Gram features, 80 MB

typedef unsigned long long ull;

static __device__ __forceinline__ ull ffma2(ull a, ull b, ull c) {
    ull d;
    asm("fma.rn.f32x2 %0, %1, %2, %3;" : "=l"(d) : "l"(a), "l"(b), "l"(c));
    return d;
}
static __device__ __forceinline__ ull add2(ull a, ull b) {
    ull d;
    asm("add.rn.f32x2 %0, %1, %2;" : "=l"(d) : "l"(a), "l"(b));
    return d;
}
static __device__ __forceinline__ void unpack2(ull v, float& lo, float& hi) {
    asm("mov.b64 {%0, %1}, %2;" : "=f"(lo), "=f"(hi) : "l"(v));
}
static __device__ __forceinline__ ull packu2(uint32_t lo, uint32_t hi) {
    ull r;
    asm("mov.b64 %0, {%1, %2};" : "=l"(r) : "r"(lo), "r"(hi));
    return r;
}
// pack two f32 into bf16x2: result = {hi -> upper16, lo -> lower16}
static __device__ __forceinline__ uint32_t bf2(float hi, float lo) {
    uint32_t r;
    asm("cvt.rn.bf16x2.f32 %0, %1, %2;" : "=r"(r) : "f"(hi), "f"(lo));
    return r;
}
static __device__ __forceinline__ float softplusf(float y) {
    return fmaxf(y, 0.0f) + log1pf(expf(-fabsf(y)));
}

// Gram sweep: lane's row in a[10] (f32x2 pairs), all rows staged in srow[400].
// Produces g[j] = dot(row_lane, row_j), j = 0..19, via broadcast LDS.128.
static __device__ __forceinline__ void gram_sweep(const ull* __restrict__ a,
                                                  const float* __restrict__ srow,
                                                  float* __restrict__ g)
{
    #pragma unroll
    for (int j = 0; j < NDIM; j++) {
        const ulonglong2* rj = (const ulonglong2*)(srow + j * NDIM);
        ulonglong2 b0 = rj[0], b1 = rj[1], b2 = rj[2], b3 = rj[3], b4 = rj[4];
        ull p0 = 0, p1 = 0;
        p0 = ffma2(a[0], b0.x, p0);  p1 = ffma2(a[1], b0.y, p1);
        p0 = ffma2(a[2], b1.x, p0);  p1 = ffma2(a[3], b1.y, p1);
        p0 = ffma2(a[4], b2.x, p0);  p1 = ffma2(a[5], b2.y, p1);
        p0 = ffma2(a[6], b3.x, p0);  p1 = ffma2(a[7], b3.y, p1);
        p0 = ffma2(a[8], b4.x, p0);  p1 = ffma2(a[9], b4.y, p1);
        float lo, hi;
        unpack2(add2(p0, p1), lo, hi);
        g[j] = lo + hi;
    }
}

// ── K1: Gram features for every vocab word of W_context ──
__global__ __launch_bounds__(256)
void w2dm_hgram(const float* __restrict__ Wc, int vocab)
{
    __shared__ __align__(16) float s_rows[8][ROWLEN];
    const int w    = threadIdx.x >> 5;
    const int lane = threadIdx.x & 31;
    const int word = blockIdx.x * 8 + w;
    if (word >= vocab || word >= VOCAB_MAX) return;

    const int row = (lane < NDIM) ? lane : 0;
    const float4* src = (const float4*)(Wc + (size_t)word * ROWLEN + row * NDIM);
    float4 v0 = src[0], v1 = src[1], v2 = src[2], v3 = src[3], v4 = src[4];
    if (lane < NDIM) {
        float4* dst = (float4*)(s_rows[w] + row * NDIM);
        dst[0] = v0; dst[1] = v1; dst[2] = v2; dst[3] = v3; dst[4] = v4;
    }
    __syncwarp();

    ull a[10];
    {
        const ulonglong2* my = (const ulonglong2*)(s_rows[w] + row * NDIM);
        ulonglong2 m0 = my[0], m1 = my[1], m2 = my[2], m3 = my[3], m4 = my[4];
        a[0] = m0.x; a[1] = m0.y; a[2] = m1.x; a[3] = m1.y; a[4] = m2.x;
        a[5] = m2.y; a[6] = m3.x; a[7] = m3.y; a[8] = m4.x; a[9] = m4.y;
    }

    float g[NDIM];
    gram_sweep(a, s_rows[w], g);

    if (lane < NDIM) {
        uint32_t o[10];
        #pragma unroll
        for (int m = 0; m < 10; m++) o[m] = bf2(g[2 * m + 1], g[2 * m]);
        ull* out = (ull*)(g_hfeat + (size_t)word * ROWLEN + lane * NDIM);
        #pragma unroll
        for (int q = 0; q < 5; q++) out[q] = packu2(o[2 * q], o[2 * q + 1]);
    }
}

// ── K2: per-sample target Gram + 11 feature dots -> loss ──
__global__ __launch_bounds__(256)
void w2dm_main(const float* __restrict__ Wt,
               const int*   __restrict__ tidx,
               const int*   __restrict__ cidx,
               const int*   __restrict__ nidx,
               int kneg, int B)
{
    __shared__ __align__(16) float s_tgt[8][ROWLEN];
    __shared__ __align__(16) float s_g[8][ROWLEN];
    __shared__ int s_wi[8][12];

    const int w    = threadIdx.x >> 5;
    const int lane = threadIdx.x & 31;
    const int b    = blockIdx.x * 8 + w;
    if (b >= B) return;

    if (lane < 12) {
        int v;
        if (lane == 0)      v = tidx[b];
        else if (lane == 1) v = cidx[b];
        else                v = nidx[b * kneg + (lane - 2)];
        s_wi[w][lane] = v;
    }
    __syncwarp();

    const int row = (lane < NDIM) ? lane : 0;
    {
        const float4* src = (const float4*)(Wt + (size_t)s_wi[w][0] * ROWLEN + row * NDIM);
        float4 v0 = src[0], v1 = src[1], v2 = src[2], v3 = src[3], v4 = src[4];
        if (lane < NDIM) {
            float4* dst = (float4*)(s_tgt[w] + row * NDIM);
            dst[0] = v0; dst[1] = v1; dst[2] = v2; dst[3] = v3; dst[4] = v4;
        }
    }
    __syncwarp();

    ull a[10];
    {
        const ulonglong2* my = (const ulonglong2*)(s_tgt[w] + row * NDIM);
        ulonglong2 m0 = my[0], m1 = my[1], m2 = my[2], m3 = my[3], m4 = my[4];
        a[0] = m0.x; a[1] = m0.y; a[2] = m1.x; a[3] = m1.y; a[4] = m2.x;
        a[5] = m2.y; a[6] = m3.x; a[7] = m3.y; a[8] = m4.x; a[9] = m4.y;
    }

    float g[NDIM];
    gram_sweep(a, s_tgt[w], g);

    if (lane < NDIM) {
        float2* gd = (float2*)(s_g[w] + row * NDIM);
        #pragma unroll
        for (int q = 0; q < 10; q++) gd[q] = make_float2(g[2 * q], g[2 * q + 1]);
    }
    __syncwarp();

    float loss = 0.0f;
    #pragma unroll 1
    for (int r = 0; r < NMATS; r++) {
        const uint32_t* hp = (const uint32_t*)(g_hfeat + (size_t)s_wi[w][1 + r] * ROWLEN);
        ull p = 0;
        #pragma unroll
        for (int it = 0; it < 7; it++) {
            int m = lane + it * 32;                     // u32 pair index, 200 total
            if (m < 200) {
                uint32_t v = hp[m];                      // coalesced LDG
                ull hf = packu2(v << 16, v & 0xFFFF0000u);        // f32x2 of bf16 pair
                ull gf = *(const ull*)(s_g[w] + 2 * m);           // matching G pair
                p = ffma2(hf, gf, p);
            }
        }
        float lo, hi;
        unpack2(p, lo, hi);
        float part = lo + hi;
        #pragma unroll
        for (int d = 16; d; d >>= 1)
            part += __shfl_xor_sync(0xffffffffu, part, d);
        loss += (r == 0) ? softplusf(-part) : softplusf(part);
    }

    if (lane == 0) g_partials[b] = loss;
}

// ── K3: deterministic fixed-order mean ──
__global__ __launch_bounds__(1024)
void w2dm_reduce(float* __restrict__ out, int B)
{
    __shared__ float s[1024];
    const int t = threadIdx.x;
    float acc = 0.0f;
    const int n4 = B >> 2;
    const float4* p = (const float4*)g_partials;
    for (int i = t; i < n4; i += 1024) {
        float4 v = p[i];
        acc += (v.x + v.y) + (v.z + v.w);
    }
    s[t] = acc;
    __syncthreads();
    #pragma unroll
    for (int w = 512; w > 0; w >>= 1) {
        if (t < w) s[t] += s[t + w];
        __syncthreads();
    }
    if (t == 0) out[0] = s[0] / (float)B;
}

extern "C" void kernel_launch(void* const* d_in, const int* in_sizes, int n_in,
                              void* d_out, int out_size)
{
    const float* Wt   = (const float*)d_in[0];
    const float* Wc   = (const float*)d_in[1];
    const int*   tidx = (const int*)d_in[2];
    const int*   cidx = (const int*)d_in[3];
    const int*   nidx = (const int*)d_in[4];

    int vocab = in_sizes[1] / ROWLEN;
    int B = in_sizes[2];
    if (B > BMAX) B = BMAX;
    int kneg = in_sizes[4] / (B > 0 ? B : 1);

    w2dm_hgram<<<(vocab + 7) / 8, 256>>>(Wc, vocab);
    w2dm_main<<<(B + 7) / 8, 256>>>(Wt, tidx, cidx, nidx, kneg, B);
    w2dm_reduce<<<1, 1024>>>((float*)d_out, B);
}

// round 6
// speedup vs baseline: 1.5920x; 1.0337x over previous
#include <cuda_runtime.h>
#include <cstdint>

// Word2DM via Gram features:
//   sim(b,r) = ||Bt^T X||_F^2 = <Bt Bt^T, X X^T>  (row-Gram matrices, 20x20)
// K1: bf16 Gram features for all vocab words of W_context (coalesced layout).
// K2: per sample: target Gram on the fly + 11 coalesced feature dots -> loss.
// K3: fixed-order mean.
//
// Round 6: all staging/store access patterns coalesced; only the essential
// 100-wavefront broadcast sweep remains as L1 load per warp.

#define NDIM      20
#define ROWLEN    400
#define NMATS     11
#define BMAX      32768
#define VOCAB_MAX 100000

__device__ float    g_partials[BMAX];
// layout: u32 index word*200 + q*20 + i  holds bf16x2 {G[i][2q], G[i][2q+1]}
__device__ uint32_t g_hfeat[(size_t)VOCAB_MAX * 200];

typedef unsigned long long ull;

static __device__ __forceinline__ ull ffma2(ull a, ull b, ull c) {
    ull d;
    asm("fma.rn.f32x2 %0, %1, %2, %3;" : "=l"(d) : "l"(a), "l"(b), "l"(c));
    return d;
}
static __device__ __forceinline__ ull add2(ull a, ull b) {
    ull d;
    asm("add.rn.f32x2 %0, %1, %2;" : "=l"(d) : "l"(a), "l"(b));
    return d;
}
static __device__ __forceinline__ void unpack2(ull v, float& lo, float& hi) {
    asm("mov.b64 {%0, %1}, %2;" : "=f"(lo), "=f"(hi) : "l"(v));
}
static __device__ __forceinline__ ull packu2(uint32_t lo, uint32_t hi) {
    ull r;
    asm("mov.b64 %0, {%1, %2};" : "=l"(r) : "r"(lo), "r"(hi));
    return r;
}
// pack two f32 into bf16x2 (hi -> upper16, lo -> lower16)
static __device__ __forceinline__ uint32_t bf2(float hi, float lo) {
    uint32_t r;
    asm("cvt.rn.bf16x2.f32 %0, %1, %2;" : "=r"(r) : "f"(hi), "f"(lo));
    return r;
}
static __device__ __forceinline__ float softplusf(float y) {
    return fmaxf(y, 0.0f) + log1pf(expf(-fabsf(y)));
}

// coalesced 1600B row stage: warp copies word-row (100 float4) into smem
static __device__ __forceinline__ void stage_row(float* __restrict__ dst,
                                                 const float* __restrict__ src,
                                                 int lane)
{
    const float4* s = (const float4*)src;
    float4*       d = (float4*)dst;
    d[lane]      = s[lane];
    d[lane + 32] = s[lane + 32];
    d[lane + 64] = s[lane + 64];
    if (lane < 4) d[lane + 96] = s[lane + 96];
}

// Gram sweep: lane's row in a[10] (f32x2 pairs), all rows staged in srow[400].
// g[j] = dot(row_lane, row_j) via broadcast LDS.128 (the essential 100 wf).
static __device__ __forceinline__ void gram_sweep(const ull* __restrict__ a,
                                                  const float* __restrict__ srow,
                                                  float* __restrict__ g)
{
    #pragma unroll
    for (int j = 0; j < NDIM; j++) {
        const ulonglong2* rj = (const ulonglong2*)(srow + j * NDIM);
        ulonglong2 b0 = rj[0], b1 = rj[1], b2 = rj[2], b3 = rj[3], b4 = rj[4];
        ull p0 = 0, p1 = 0;
        p0 = ffma2(a[0], b0.x, p0);  p1 = ffma2(a[1], b0.y, p1);
        p0 = ffma2(a[2], b1.x, p0);  p1 = ffma2(a[3], b1.y, p1);
        p0 = ffma2(a[4], b2.x, p0);  p1 = ffma2(a[5], b2.y, p1);
        p0 = ffma2(a[6], b3.x, p0);  p1 = ffma2(a[7], b3.y, p1);
        p0 = ffma2(a[8], b4.x, p0);  p1 = ffma2(a[9], b4.y, p1);
        float lo, hi;
        unpack2(add2(p0, p1), lo, hi);
        g[j] = lo + hi;
    }
}

static __device__ __forceinline__ void load_own_row(ull* __restrict__ a,
                                                    const float* __restrict__ srow,
                                                    int row)
{
    const ulonglong2* my = (const ulonglong2*)(srow + row * NDIM);
    ulonglong2 m0 = my[0], m1 = my[1], m2 = my[2], m3 = my[3], m4 = my[4];
    a[0] = m0.x; a[1] = m0.y; a[2] = m1.x; a[3] = m1.y; a[4] = m2.x;
    a[5] = m2.y; a[6] = m3.x; a[7] = m3.y; a[8] = m4.x; a[9] = m4.y;
}

// ── K1: Gram features for every vocab word of W_context ──
__global__ __launch_bounds__(256)
void w2dm_hgram(const float* __restrict__ Wc, int vocab)
{
    __shared__ __align__(16) float s_rows[8][ROWLEN];
    const int w    = threadIdx.x >> 5;
    const int lane = threadIdx.x & 31;
    const int word = blockIdx.x * 8 + w;
    if (word >= vocab || word >= VOCAB_MAX) return;

    stage_row(s_rows[w], Wc + (size_t)word * ROWLEN, lane);
    __syncwarp();

    const int row = (lane < NDIM) ? lane : 0;
    ull a[10];
    load_own_row(a, s_rows[w], row);

    float g[NDIM];
    gram_sweep(a, s_rows[w], g);

    if (lane < NDIM) {
        uint32_t* out = g_hfeat + (size_t)word * 200 + lane;
        #pragma unroll
        for (int q = 0; q < 10; q++)
            out[q * 20] = bf2(g[2 * q + 1], g[2 * q]);   // coalesced across lanes
    }
}

// ── K2: per-sample target Gram + 11 feature dots -> loss ──
__global__ __launch_bounds__(256)
void w2dm_main(const float* __restrict__ Wt,
               const int*   __restrict__ tidx,
               const int*   __restrict__ cidx,
               const int*   __restrict__ nidx,
               int kneg, int B)
{
    __shared__ __align__(16) float s_tgt[8][ROWLEN];
    __shared__ __align__(16) float s_g[8][ROWLEN];      // f32 pairs in feature layout
    __shared__ int s_wi[8][12];

    const int w    = threadIdx.x >> 5;
    const int lane = threadIdx.x & 31;
    const int b    = blockIdx.x * 8 + w;
    if (b >= B) return;

    if (lane < 12) {
        int v;
        if (lane == 0)      v = tidx[b];
        else if (lane == 1) v = cidx[b];
        else                v = nidx[b * kneg + (lane - 2)];
        s_wi[w][lane] = v;
    }
    __syncwarp();

    stage_row(s_tgt[w], Wt + (size_t)s_wi[w][0] * ROWLEN, lane);
    __syncwarp();

    const int row = (lane < NDIM) ? lane : 0;
    ull a[10];
    load_own_row(a, s_tgt[w], row);

    float g[NDIM];
    gram_sweep(a, s_tgt[w], g);

    // scratch target-Gram in the SAME layout as g_hfeat: pair m = q*20 + i
    if (lane < NDIM) {
        float2* gd = (float2*)s_g[w];
        #pragma unroll
        for (int q = 0; q < 10; q++)
            gd[q * 20 + lane] = make_float2(g[2 * q], g[2 * q + 1]);
    }
    __syncwarp();

    float loss = 0.0f;
    #pragma unroll 1
    for (int r = 0; r < NMATS; r++) {
        const uint32_t* hp = g_hfeat + (size_t)s_wi[w][1 + r] * 200;
        ull p = 0;
        #pragma unroll
        for (int it = 0; it < 7; it++) {
            int m = lane + it * 32;                 // 200 u32 pairs, coalesced
            if (m < 200) {
                uint32_t v = hp[m];
                ull hf = packu2(v << 16, v & 0xFFFF0000u);   // bf16 pair -> f32x2
                ull gf = *(const ull*)(s_g[w] + 2 * m);
                p = ffma2(hf, gf, p);
            }
        }
        float lo, hi;
        unpack2(p, lo, hi);
        float part = lo + hi;
        #pragma unroll
        for (int d = 16; d; d >>= 1)
            part += __shfl_xor_sync(0xffffffffu, part, d);
        loss += (r == 0) ? softplusf(-part) : softplusf(part);
    }

    if (lane == 0) g_partials[b] = loss;
}

// ── K3: deterministic fixed-order mean ──
__global__ __launch_bounds__(1024)
void w2dm_reduce(float* __restrict__ out, int B)
{
    __shared__ float s[1024];
    const int t = threadIdx.x;
    float acc = 0.0f;
    const int n4 = B >> 2;
    const float4* p = (const float4*)g_partials;
    for (int i = t; i < n4; i += 1024) {
        float4 v = p[i];
        acc += (v.x + v.y) + (v.z + v.w);
    }
    s[t] = acc;
    __syncthreads();
    #pragma unroll
    for (int w = 512; w > 0; w >>= 1) {
        if (t < w) s[t] += s[t + w];
        __syncthreads();
    }
    if (t == 0) out[0] = s[0] / (float)B;
}

extern "C" void kernel_launch(void* const* d_in, const int* in_sizes, int n_in,
                              void* d_out, int out_size)
{
    const float* Wt   = (const float*)d_in[0];
    const float* Wc   = (const float*)d_in[1];
    const int*   tidx = (const int*)d_in[2];
    const int*   cidx = (const int*)d_in[3];
    const int*   nidx = (const int*)d_in[4];

    int vocab = in_sizes[1] / ROWLEN;
    int B = in_sizes[2];
    if (B > BMAX) B = BMAX;
    int kneg = in_sizes[4] / (B > 0 ? B : 1);

    w2dm_hgram<<<(vocab + 7) / 8, 256>>>(Wc, vocab);
    w2dm_main<<<(B + 7) / 8, 256>>>(Wt, tidx, cidx, nidx, kneg, B);
    w2dm_reduce<<<1, 1024>>>((float*)d_out, B);
}

// round 7
// speedup vs baseline: 2.2482x; 1.4122x over previous
#include <cuda_runtime.h>
#include <cstdint>

// Word2DM via Gram features:
//   sim(b,r) = ||Bt^T X||_F^2 = <Bt Bt^T, X X^T>  (row-Gram matrices, 20x20)
// K1: bf16 Gram sweep -> pair-aligned-triangle bf16 features for all vocab words.
// K2: per sample: target Gram (bf16 sweep) + 11 triangle dots (weights folded) -> loss.
// K3: fixed-order mean.

#define NDIM      20
#define NMATS     11
#define BMAX      32768
#define VOCAB_MAX 100000
#define TPAIRS    110          // padded-triangle u32 pairs per word
#define TSTRIDE   112          // u32 stride per word (16B aligned)

__device__ float    g_partials[BMAX];
__device__ uint32_t g_hfeat[(size_t)VOCAB_MAX * TSTRIDE];   // 44.8 MB, L2-resident

typedef unsigned long long ull;

static __device__ __forceinline__ ull ffma2(ull a, ull b, ull c) {
    ull d;
    asm("fma.rn.f32x2 %0, %1, %2, %3;" : "=l"(d) : "l"(a), "l"(b), "l"(c));
    return d;
}
static __device__ __forceinline__ uint32_t hfma2(uint32_t a, uint32_t b, uint32_t c) {
    uint32_t d;
    asm("fma.rn.bf16x2 %0, %1, %2, %3;" : "=r"(d) : "r"(a), "r"(b), "r"(c));
    return d;
}
static __device__ __forceinline__ void unpack2(ull v, float& lo, float& hi) {
    asm("mov.b64 {%0, %1}, %2;" : "=f"(lo), "=f"(hi) : "l"(v));
}
static __device__ __forceinline__ ull packu2(uint32_t lo, uint32_t hi) {
    ull r;
    asm("mov.b64 %0, {%1, %2};" : "=l"(r) : "r"(lo), "r"(hi));
    return r;
}
// pack two f32 into bf16x2 (hi -> upper16, lo -> lower16)
static __device__ __forceinline__ uint32_t bf2(float hi, float lo) {
    uint32_t r;
    asm("cvt.rn.bf16x2.f32 %0, %1, %2;" : "=r"(r) : "f"(hi), "f"(lo));
    return r;
}
// bf16x2 pair -> two f32 (exact, bit-shift)
static __device__ __forceinline__ void bfsplit(uint32_t v, float& lo, float& hi) {
    lo = __uint_as_float(v << 16);
    hi = __uint_as_float(v & 0xFFFF0000u);
}
static __device__ __forceinline__ float softplusf(float y) {
    return fmaxf(y, 0.0f) + log1pf(expf(-fabsf(y)));
}

// triangle row start (u32 units): R(2t)=t*(21-t), R(2t+1)=20t+10-t*t
static __device__ __forceinline__ int trow(int i) {
    int t = i >> 1;
    return (i & 1) ? (20 * t + 10 - t * t) : (t * (21 - t));
}

// stage one word (400 f32, 1600B) coalesced -> bf16 rows, 48B row stride
// dst16: per-warp base (u16 units), 20 rows x 24 u16
static __device__ __forceinline__ void stage_bf16(uint16_t* __restrict__ dst16,
                                                  const float* __restrict__ src,
                                                  int lane)
{
    const float4* s = (const float4*)src;
    #pragma unroll
    for (int k = 0; k < 4; k++) {
        int f = lane + 32 * k;
        if (f < 100) {
            float4 v = s[f];
            int row = f / 5, q = f % 5;
            uint32_t lo = bf2(v.y, v.x);
            uint32_t hi = bf2(v.w, v.z);
            *(ull*)(dst16 + row * 24 + q * 4) = packu2(lo, hi);
        }
    }
}

// bf16 Gram sweep: lane's row in a[10] (bf16x2), rows staged at base16 (48B stride).
// g[j] = dot(row_lane, row_j), f32 outputs.
static __device__ __forceinline__ void gram_sweep_bf16(const uint32_t* __restrict__ a,
                                                       const uint16_t* __restrict__ base16,
                                                       float* __restrict__ g)
{
    #pragma unroll
    for (int j = 0; j < NDIM; j++) {
        const uint16_t* rj = base16 + j * 24;
        uint4 b0 = *(const uint4*)rj;          // k 0..3
        uint4 b1 = *(const uint4*)(rj + 8);    // k 4..7
        uint2 b2 = *(const uint2*)(rj + 16);   // k 8..9
        uint32_t p0 = 0, p1 = 0;
        p0 = hfma2(a[0], b0.x, p0);  p1 = hfma2(a[1], b0.y, p1);
        p0 = hfma2(a[2], b0.z, p0);  p1 = hfma2(a[3], b0.w, p1);
        p0 = hfma2(a[4], b1.x, p0);  p1 = hfma2(a[5], b1.y, p1);
        p0 = hfma2(a[6], b1.z, p0);  p1 = hfma2(a[7], b1.w, p1);
        p0 = hfma2(a[8], b2.x, p0);  p1 = hfma2(a[9], b2.y, p1);
        float l0, h0, l1, h1;
        bfsplit(p0, l0, h0);
        bfsplit(p1, l1, h1);
        g[j] = (l0 + h0) + (l1 + h1);
    }
}

static __device__ __forceinline__ void load_own_row_bf16(uint32_t* __restrict__ a,
                                                         const uint16_t* __restrict__ base16,
                                                         int row)
{
    const uint16_t* r = base16 + row * 24;
    uint4 m0 = *(const uint4*)r;
    uint4 m1 = *(const uint4*)(r + 8);
    uint2 m2 = *(const uint2*)(r + 16);
    a[0] = m0.x; a[1] = m0.y; a[2] = m0.z; a[3] = m0.w;
    a[4] = m1.x; a[5] = m1.y; a[6] = m1.z; a[7] = m1.w;
    a[8] = m2.x; a[9] = m2.y;
}

// ── K1: triangle Gram features for every vocab word of W_context ──
__global__ __launch_bounds__(256)
void w2dm_hgram(const float* __restrict__ Wc, int vocab)
{
    __shared__ __align__(16) uint16_t s_rows[8][480];    // 20 rows x 24 u16 per word
    const int w    = threadIdx.x >> 5;
    const int lane = threadIdx.x & 31;
    const int word = blockIdx.x * 8 + w;
    if (word >= vocab || word >= VOCAB_MAX) return;

    stage_bf16(s_rows[w], Wc + (size_t)word * 400, lane);
    __syncwarp();

    const int row = (lane < NDIM) ? lane : 0;
    uint32_t a[10];
    load_own_row_bf16(a, s_rows[w], row);

    float g[NDIM];
    gram_sweep_bf16(a, s_rows[w], g);

    if (lane < NDIM) {
        const int qi = lane >> 1;                  // first absolute pair for this row
        uint32_t* out = g_hfeat + (size_t)word * TSTRIDE + trow(lane) - qi;
        #pragma unroll
        for (int q = 0; q < 10; q++)
            if (q >= qi)
                out[q] = bf2(g[2 * q + 1], g[2 * q]);   // constant reg indices
    }
}

// ── K2: per-sample target Gram + 11 triangle dots -> loss ──
__global__ __launch_bounds__(256)
void w2dm_main(const float* __restrict__ Wt,
               const int*   __restrict__ tidx,
               const int*   __restrict__ cidx,
               const int*   __restrict__ nidx,
               int kneg, int B)
{
    __shared__ __align__(16) uint16_t s_rows[8][480];
    __shared__ __align__(16) float2   s_g[8][TSTRIDE];   // weighted target pairs (f32x2)
    __shared__ int s_wi[8][12];

    const int w    = threadIdx.x >> 5;
    const int lane = threadIdx.x & 31;
    const int b    = blockIdx.x * 8 + w;
    if (b >= B) return;

    if (lane < 12) {
        int v;
        if (lane == 0)      v = tidx[b];
        else if (lane == 1) v = cidx[b];
        else                v = nidx[b * kneg + (lane - 2)];
        s_wi[w][lane] = v;
    }
    __syncwarp();

    stage_bf16(s_rows[w], Wt + (size_t)s_wi[w][0] * 400, lane);
    __syncwarp();

    const int row = (lane < NDIM) ? lane : 0;
    uint32_t a[10];
    load_own_row_bf16(a, s_rows[w], row);

    float g[NDIM];
    gram_sweep_bf16(a, s_rows[w], g);

    // weighted target pairs in the SAME absolute-pair triangle layout:
    //   pair q of row i covers (j0,j1) = (2q, 2q+1); weights: j<i ->0, j==i ->1, j>i ->2
    if (lane < NDIM) {
        const int i  = lane;
        const int qi = i >> 1;
        float2* gd = &s_g[w][trow(i) - qi];
        #pragma unroll
        for (int q = 0; q < 10; q++) {
            if (q >= qi) {
                float w0, w1;
                if (q > qi)            { w0 = 2.0f; w1 = 2.0f; }
                else if ((i & 1) == 0) { w0 = 1.0f; w1 = 2.0f; }   // (i, i+1)
                else                   { w0 = 0.0f; w1 = 1.0f; }   // (i-1, i)
                gd[q] = make_float2(w0 * g[2 * q], w1 * g[2 * q + 1]);
            }
        }
    }
    __syncwarp();

    float loss = 0.0f;
    #pragma unroll 1
    for (int r = 0; r < NMATS; r++) {
        const uint32_t* hp = g_hfeat + (size_t)s_wi[w][1 + r] * TSTRIDE;
        ull p = 0;
        #pragma unroll
        for (int it = 0; it < 4; it++) {
            int m = lane + it * 32;                 // 110 u32 pairs, coalesced
            if (m < TPAIRS) {
                uint32_t v = hp[m];
                ull hf = packu2(v << 16, v & 0xFFFF0000u);   // bf16 pair -> f32x2
                ull gf = *(const ull*)&s_g[w][m];
                p = ffma2(hf, gf, p);
            }
        }
        float lo, hi;
        unpack2(p, lo, hi);
        float part = lo + hi;
        #pragma unroll
        for (int d = 16; d; d >>= 1)
            part += __shfl_xor_sync(0xffffffffu, part, d);
        loss += (r == 0) ? softplusf(-part) : softplusf(part);
    }

    if (lane == 0) g_partials[b] = loss;
}

// ── K3: deterministic fixed-order mean ──
__global__ __launch_bounds__(1024)
void w2dm_reduce(float* __restrict__ out, int B)
{
    __shared__ float s[1024];
    const int t = threadIdx.x;
    float acc = 0.0f;
    const int n4 = B >> 2;
    const float4* p = (const float4*)g_partials;
    for (int i = t; i < n4; i += 1024) {
        float4 v = p[i];
        acc += (v.x + v.y) + (v.z + v.w);
    }
    s[t] = acc;
    __syncthreads();
    #pragma unroll
    for (int w = 512; w > 0; w >>= 1) {
        if (t < w) s[t] += s[t + w];
        __syncthreads();
    }
    if (t == 0) out[0] = s[0] / (float)B;
}

extern "C" void kernel_launch(void* const* d_in, const int* in_sizes, int n_in,
                              void* d_out, int out_size)
{
    const float* Wt   = (const float*)d_in[0];
    const float* Wc   = (const float*)d_in[1];
    const int*   tidx = (const int*)d_in[2];
    const int*   cidx = (const int*)d_in[3];
    const int*   nidx = (const int*)d_in[4];

    int vocab = in_sizes[1] / 400;
    int B = in_sizes[2];
    if (B > BMAX) B = BMAX;
    int kneg = in_sizes[4] / (B > 0 ? B : 1);

    w2dm_hgram<<<(vocab + 7) / 8, 256>>>(Wc, vocab);
    w2dm_main<<<(B + 7) / 8, 256>>>(Wt, tidx, cidx, nidx, kneg, B);
    w2dm_reduce<<<1, 1024>>>((float*)d_out, B);
}

// round 9
// speedup vs baseline: 2.3620x; 1.0506x over previous
#include <cuda_runtime.h>
#include <cstdint>

// Word2DM via Gram features:
//   sim(b,r) = ||Bt^T X||_F^2 = <Bt Bt^T, X X^T>  (row-Gram matrices, 20x20)
// K1: bf16 Gram sweep -> pair-aligned-triangle bf16 features (streamed Wc via __ldcs
//     so the feature table stays L2-resident for K2).
// K2: per sample: target Gram (bf16) + 11 triangle dots, all-bf16 datapath -> loss.
// K3: fixed-order mean.

#define NDIM      20
#define NMATS     11
#define BMAX      32768
#define VOCAB_MAX 100000
#define TPAIRS    110          // padded-triangle u32 pairs per word
#define TSTRIDE   112          // u32 stride per word (16B aligned)

__device__ float    g_partials[BMAX];
__device__ uint32_t g_hfeat[(size_t)VOCAB_MAX * TSTRIDE];   // 44.8 MB

typedef unsigned long long ull;

static __device__ __forceinline__ uint32_t hfma2(uint32_t a, uint32_t b, uint32_t c) {
    uint32_t d;
    asm("fma.rn.bf16x2 %0, %1, %2, %3;" : "=r"(d) : "r"(a), "r"(b), "r"(c));
    return d;
}
static __device__ __forceinline__ uint32_t hadd2(uint32_t a, uint32_t b) {
    uint32_t d;
    asm("add.bf16x2 %0, %1, %2;" : "=r"(d) : "r"(a), "r"(b));
    return d;
}
static __device__ __forceinline__ uint32_t hmul2(uint32_t a, uint32_t b) {
    uint32_t d;
    asm("mul.bf16x2 %0, %1, %2;" : "=r"(d) : "r"(a), "r"(b));
    return d;
}
static __device__ __forceinline__ uint32_t prmt(uint32_t a, uint32_t b, uint32_t sel) {
    uint32_t d;
    asm("prmt.b32 %0, %1, %2, %3;" : "=r"(d) : "r"(a), "r"(b), "r"(sel));
    return d;
}
static __device__ __forceinline__ ull packu2(uint32_t lo, uint32_t hi) {
    ull r;
    asm("mov.b64 %0, {%1, %2};" : "=l"(r) : "r"(lo), "r"(hi));
    return r;
}
static __device__ __forceinline__ uint32_t bf2(float hi, float lo) {
    uint32_t r;
    asm("cvt.rn.bf16x2.f32 %0, %1, %2;" : "=r"(r) : "f"(hi), "f"(lo));
    return r;
}
static __device__ __forceinline__ float softplusf(float y) {
    return fmaxf(y, 0.0f) + log1pf(expf(-fabsf(y)));
}

// triangle row start (u32 units): R(2t)=t*(21-t), R(2t+1)=20t+10-t*t
static __device__ __forceinline__ int trow(int i) {
    int t = i >> 1;
    return (i & 1) ? (20 * t + 10 - t * t) : (t * (21 - t));
}

// stage one word (400 f32, streamed/evict-first) -> bf16 rows, 48B row stride
static __device__ __forceinline__ void stage_bf16(uint16_t* __restrict__ dst16,
                                                  const float* __restrict__ src,
                                                  int lane)
{
    const float4* s = (const float4*)src;
    #pragma unroll
    for (int k = 0; k < 4; k++) {
        int f = lane + 32 * k;
        if (f < 100) {
            float4 v = __ldcs(s + f);               // evict-first: protect L2 table
            int row = f / 5, q = f % 5;
            uint32_t lo = bf2(v.y, v.x);
            uint32_t hi = bf2(v.w, v.z);
            *(ull*)(dst16 + row * 24 + q * 4) = packu2(lo, hi);
        }
    }
}

// bf16 Gram sweep: lane's row in a[10] (bf16x2), rows at base16 (48B stride).
// gsum[j]: bf16x2 with BOTH halves = dot(row_lane, row_j).
static __device__ __forceinline__ void gram_sweep_bf16(const uint32_t* __restrict__ a,
                                                       const uint16_t* __restrict__ base16,
                                                       uint32_t* __restrict__ gsum)
{
    #pragma unroll
    for (int j = 0; j < NDIM; j++) {
        const uint16_t* rj = base16 + j * 24;
        uint4 b0 = *(const uint4*)rj;
        uint4 b1 = *(const uint4*)(rj + 8);
        uint2 b2 = *(const uint2*)(rj + 16);
        uint32_t p0 = 0, p1 = 0;
        p0 = hfma2(a[0], b0.x, p0);  p1 = hfma2(a[1], b0.y, p1);
        p0 = hfma2(a[2], b0.z, p0);  p1 = hfma2(a[3], b0.w, p1);
        p0 = hfma2(a[4], b1.x, p0);  p1 = hfma2(a[5], b1.y, p1);
        p0 = hfma2(a[6], b1.z, p0);  p1 = hfma2(a[7], b1.w, p1);
        p0 = hfma2(a[8], b2.x, p0);  p1 = hfma2(a[9], b2.y, p1);
        uint32_t v = hadd2(p0, p1);
        gsum[j] = hadd2(v, prmt(v, v, 0x1032u));    // halves-sum in both halves
    }
}

static __device__ __forceinline__ void load_own_row_bf16(uint32_t* __restrict__ a,
                                                         const uint16_t* __restrict__ base16,
                                                         int row)
{
    const uint16_t* r = base16 + row * 24;
    uint4 m0 = *(const uint4*)r;
    uint4 m1 = *(const uint4*)(r + 8);
    uint2 m2 = *(const uint2*)(r + 16);
    a[0] = m0.x; a[1] = m0.y; a[2] = m0.z; a[3] = m0.w;
    a[4] = m1.x; a[5] = m1.y; a[6] = m1.z; a[7] = m1.w;
    a[8] = m2.x; a[9] = m2.y;
}

// ── K1: triangle Gram features for every vocab word of W_context ──
__global__ __launch_bounds__(256)
void w2dm_hgram(const float* __restrict__ Wc, int vocab)
{
    __shared__ __align__(16) uint16_t s_rows[8][480];
    const int w    = threadIdx.x >> 5;
    const int lane = threadIdx.x & 31;
    const int word = blockIdx.x * 8 + w;
    if (word >= vocab || word >= VOCAB_MAX) return;

    stage_bf16(s_rows[w], Wc + (size_t)word * 400, lane);
    __syncwarp();

    const int row = (lane < NDIM) ? lane : 0;
    uint32_t a[10];
    load_own_row_bf16(a, s_rows[w], row);

    uint32_t gsum[NDIM];
    gram_sweep_bf16(a, s_rows[w], gsum);

    if (lane < NDIM) {
        const int qi = lane >> 1;
        uint32_t* out = g_hfeat + (size_t)word * TSTRIDE + trow(lane) - qi;
        #pragma unroll
        for (int q = 0; q < 10; q++)
            if (q >= qi)
                out[q] = prmt(gsum[2 * q], gsum[2 * q + 1], 0x5410u);  // {lo=g2q, hi=g2q+1}
    }
}

// ── K2: per-sample target Gram + 11 triangle dots -> loss ──
__global__ __launch_bounds__(256)
void w2dm_main(const float* __restrict__ Wt,
               const int*   __restrict__ tidx,
               const int*   __restrict__ cidx,
               const int*   __restrict__ nidx,
               int kneg, int B)
{
    __shared__ __align__(16) uint16_t s_rows[8][480];
    __shared__ __align__(16) uint32_t s_g[8][TSTRIDE];   // weighted target pairs (bf16x2)
    __shared__ int s_wi[8][12];

    const int w    = threadIdx.x >> 5;
    const int lane = threadIdx.x & 31;
    const int b    = blockIdx.x * 8 + w;
    if (b >= B) return;

    if (lane < 12) {
        int v;
        if (lane == 0)      v = tidx[b];
        else if (lane == 1) v = cidx[b];
        else                v = nidx[b * kneg + (lane - 2)];
        s_wi[w][lane] = v;
    }
    __syncwarp();

    stage_bf16(s_rows[w], Wt + (size_t)s_wi[w][0] * 400, lane);
    __syncwarp();

    const int row = (lane < NDIM) ? lane : 0;
    uint32_t a[10];
    load_own_row_bf16(a, s_rows[w], row);

    uint32_t gsum[NDIM];
    gram_sweep_bf16(a, s_rows[w], gsum);

    // weighted target pairs, absolute-pair triangle layout (bf16x2):
    //   pair q of row i covers (2q, 2q+1); weights: j<i ->0, j==i ->1, j>i ->2
    if (lane < NDIM) {
        const int i  = lane;
        const int qi = i >> 1;
        uint32_t* gd = &s_g[w][trow(i) - qi];
        #pragma unroll
        for (int q = 0; q < 10; q++) {
            if (q >= qi) {
                uint32_t pair = prmt(gsum[2 * q], gsum[2 * q + 1], 0x5410u);
                uint32_t wsel = (q > qi) ? 0x40004000u                      // {2,2}
                              : ((i & 1) == 0 ? 0x40003F80u                 // {1,2}
                                              : 0x3F800000u);               // {0,1}
                gd[q] = hmul2(pair, wsel);
            }
        }
    }
    __syncwarp();

    float loss = 0.0f;
    #pragma unroll 1
    for (int r = 0; r < NMATS; r++) {
        const uint32_t* hp = g_hfeat + (size_t)s_wi[w][1 + r] * TSTRIDE;
        uint32_t p = 0;
        #pragma unroll
        for (int it = 0; it < 4; it++) {
            int m = lane + it * 32;
            if (m < TPAIRS)
                p = hfma2(hp[m], s_g[w][m], p);
        }
        #pragma unroll
        for (int d = 16; d; d >>= 1)
            p = hadd2(p, __shfl_xor_sync(0xffffffffu, p, d));
        uint32_t tsum = hadd2(p, prmt(p, p, 0x1032u));
        float part = __uint_as_float(tsum << 16);
        loss += (r == 0) ? softplusf(-part) : softplusf(part);
    }

    if (lane == 0) g_partials[b] = loss;
}

// ── K3: deterministic fixed-order mean ──
__global__ __launch_bounds__(1024)
void w2dm_reduce(float* __restrict__ out, int B)
{
    __shared__ float s[1024];
    const int t = threadIdx.x;
    float acc = 0.0f;
    const int n4 = B >> 2;
    const float4* p = (const float4*)g_partials;
    for (int i = t; i < n4; i += 1024) {
        float4 v = p[i];
        acc += (v.x + v.y) + (v.z + v.w);
    }
    s[t] = acc;
    __syncthreads();
    #pragma unroll
    for (int w = 512; w > 0; w >>= 1) {
        if (t < w) s[t] += s[t + w];
        __syncthreads();
    }
    if (t == 0) out[0] = s[0] / (float)B;
}

extern "C" void kernel_launch(void* const* d_in, const int* in_sizes, int n_in,
                              void* d_out, int out_size)
{
    const float* Wt   = (const float*)d_in[0];
    const float* Wc   = (const float*)d_in[1];
    const int*   tidx = (const int*)d_in[2];
    const int*   cidx = (const int*)d_in[3];
    const int*   nidx = (const int*)d_in[4];

    int vocab = in_sizes[1] / 400;
    int B = in_sizes[2];
    if (B > BMAX) B = BMAX;
    int kneg = in_sizes[4] / (B > 0 ? B : 1);

    w2dm_hgram<<<(vocab + 7) / 8, 256>>>(Wc, vocab);
    w2dm_main<<<(B + 7) / 8, 256>>>(Wt, tidx, cidx, nidx, kneg, B);
    w2dm_reduce<<<1, 1024>>>((float*)d_out, B);
}

// round 10
// speedup vs baseline: 2.5544x; 1.0815x over previous
#include <cuda_runtime.h>
#include <cstdint>

// Word2DM via Gram features:
//   sim(b,r) = ||Bt^T X||_F^2 = <Bt Bt^T, X X^T>  (row-Gram matrices, 20x20)
// K1: bf16 Gram sweep -> pair-aligned-triangle bf16 features (streamed via __ldcs).
// K2: per sample: target Gram + 11 triangle dots with BATCHED gathers (MLP~44),
//     fused last-block fixed-order mean.

#define NDIM      20
#define NMATS     11
#define BMAX      32768
#define VOCAB_MAX 100000
#define TPAIRS    110          // padded-triangle u32 pairs per word
#define TSTRIDE   112          // u32 stride per word (16B aligned)

__device__ float    g_partials[BMAX];
__device__ uint32_t g_hfeat[(size_t)VOCAB_MAX * TSTRIDE];   // 44.8 MB
__device__ unsigned int g_ctr;                               // replay-safe modulo counter

typedef unsigned long long ull;

static __device__ __forceinline__ uint32_t hfma2(uint32_t a, uint32_t b, uint32_t c) {
    uint32_t d;
    asm("fma.rn.bf16x2 %0, %1, %2, %3;" : "=r"(d) : "r"(a), "r"(b), "r"(c));
    return d;
}
static __device__ __forceinline__ uint32_t hadd2(uint32_t a, uint32_t b) {
    uint32_t d;
    asm("add.bf16x2 %0, %1, %2;" : "=r"(d) : "r"(a), "r"(b));
    return d;
}
static __device__ __forceinline__ uint32_t hmul2(uint32_t a, uint32_t b) {
    uint32_t d;
    asm("mul.bf16x2 %0, %1, %2;" : "=r"(d) : "r"(a), "r"(b));
    return d;
}
static __device__ __forceinline__ uint32_t prmt(uint32_t a, uint32_t b, uint32_t sel) {
    uint32_t d;
    asm("prmt.b32 %0, %1, %2, %3;" : "=r"(d) : "r"(a), "r"(b), "r"(sel));
    return d;
}
static __device__ __forceinline__ ull packu2(uint32_t lo, uint32_t hi) {
    ull r;
    asm("mov.b64 %0, {%1, %2};" : "=l"(r) : "r"(lo), "r"(hi));
    return r;
}
static __device__ __forceinline__ uint32_t bf2(float hi, float lo) {
    uint32_t r;
    asm("cvt.rn.bf16x2.f32 %0, %1, %2;" : "=r"(r) : "f"(hi), "f"(lo));
    return r;
}
static __device__ __forceinline__ float softplusf(float y) {
    return fmaxf(y, 0.0f) + log1pf(expf(-fabsf(y)));
}

// triangle row start (u32 units): R(2t)=t*(21-t), R(2t+1)=20t+10-t*t
static __device__ __forceinline__ int trow(int i) {
    int t = i >> 1;
    return (i & 1) ? (20 * t + 10 - t * t) : (t * (21 - t));
}

// stage one word (400 f32, streamed/evict-first) -> bf16 rows, 48B row stride
static __device__ __forceinline__ void stage_bf16(uint16_t* __restrict__ dst16,
                                                  const float* __restrict__ src,
                                                  int lane)
{
    const float4* s = (const float4*)src;
    #pragma unroll
    for (int k = 0; k < 4; k++) {
        int f = lane + 32 * k;
        if (f < 100) {
            float4 v = __ldcs(s + f);               // evict-first: protect L2 table
            int row = f / 5, q = f % 5;
            uint32_t lo = bf2(v.y, v.x);
            uint32_t hi = bf2(v.w, v.z);
            *(ull*)(dst16 + row * 24 + q * 4) = packu2(lo, hi);
        }
    }
}

// bf16 Gram sweep: lane's row in a[10] (bf16x2), rows at base16 (48B stride).
// gsum[j]: bf16x2 with BOTH halves = dot(row_lane, row_j).
static __device__ __forceinline__ void gram_sweep_bf16(const uint32_t* __restrict__ a,
                                                       const uint16_t* __restrict__ base16,
                                                       uint32_t* __restrict__ gsum)
{
    #pragma unroll
    for (int j = 0; j < NDIM; j++) {
        const uint16_t* rj = base16 + j * 24;
        uint4 b0 = *(const uint4*)rj;
        uint4 b1 = *(const uint4*)(rj + 8);
        uint2 b2 = *(const uint2*)(rj + 16);
        uint32_t p0 = 0, p1 = 0;
        p0 = hfma2(a[0], b0.x, p0);  p1 = hfma2(a[1], b0.y, p1);
        p0 = hfma2(a[2], b0.z, p0);  p1 = hfma2(a[3], b0.w, p1);
        p0 = hfma2(a[4], b1.x, p0);  p1 = hfma2(a[5], b1.y, p1);
        p0 = hfma2(a[6], b1.z, p0);  p1 = hfma2(a[7], b1.w, p1);
        p0 = hfma2(a[8], b2.x, p0);  p1 = hfma2(a[9], b2.y, p1);
        uint32_t v = hadd2(p0, p1);
        gsum[j] = hadd2(v, prmt(v, v, 0x1032u));    // halves-sum in both halves
    }
}

static __device__ __forceinline__ void load_own_row_bf16(uint32_t* __restrict__ a,
                                                         const uint16_t* __restrict__ base16,
                                                         int row)
{
    const uint16_t* r = base16 + row * 24;
    uint4 m0 = *(const uint4*)r;
    uint4 m1 = *(const uint4*)(r + 8);
    uint2 m2 = *(const uint2*)(r + 16);
    a[0] = m0.x; a[1] = m0.y; a[2] = m0.z; a[3] = m0.w;
    a[4] = m1.x; a[5] = m1.y; a[6] = m1.z; a[7] = m1.w;
    a[8] = m2.x; a[9] = m2.y;
}

// ── K1: triangle Gram features for every vocab word of W_context ──
__global__ __launch_bounds__(256)
void w2dm_hgram(const float* __restrict__ Wc, int vocab)
{
    __shared__ __align__(16) uint16_t s_rows[8][480];
    const int w    = threadIdx.x >> 5;
    const int lane = threadIdx.x & 31;
    const int word = blockIdx.x * 8 + w;
    if (word >= vocab || word >= VOCAB_MAX) return;

    stage_bf16(s_rows[w], Wc + (size_t)word * 400, lane);
    __syncwarp();

    const int row = (lane < NDIM) ? lane : 0;
    uint32_t a[10];
    load_own_row_bf16(a, s_rows[w], row);

    uint32_t gsum[NDIM];
    gram_sweep_bf16(a, s_rows[w], gsum);

    if (lane < NDIM) {
        const int qi = lane >> 1;
        uint32_t* out = g_hfeat + (size_t)word * TSTRIDE + trow(lane) - qi;
        #pragma unroll
        for (int q = 0; q < 10; q++)
            if (q >= qi)
                out[q] = prmt(gsum[2 * q], gsum[2 * q + 1], 0x5410u);  // {lo=g2q, hi=g2q+1}
    }
}

// ── K2: per-sample target Gram + 11 batched triangle dots -> loss; fused mean ──
__global__ __launch_bounds__(256)
void w2dm_main(const float* __restrict__ Wt,
               const int*   __restrict__ tidx,
               const int*   __restrict__ cidx,
               const int*   __restrict__ nidx,
               int kneg, int B, float* __restrict__ out)
{
    __shared__ __align__(16) uint16_t s_rows[8][480];
    __shared__ __align__(16) uint32_t s_g[8][TSTRIDE];   // weighted target pairs (bf16x2)
    __shared__ int s_wi[8][12];
    __shared__ unsigned s_last;

    const int w    = threadIdx.x >> 5;
    const int lane = threadIdx.x & 31;
    const int b    = blockIdx.x * 8 + w;

    if (b < B) {
        if (lane < 12) {
            int v;
            if (lane == 0)      v = tidx[b];
            else if (lane == 1) v = cidx[b];
            else                v = nidx[b * kneg + (lane - 2)];
            s_wi[w][lane] = v;
        }
        __syncwarp();

        stage_bf16(s_rows[w], Wt + (size_t)s_wi[w][0] * 400, lane);
        __syncwarp();

        const int row = (lane < NDIM) ? lane : 0;
        uint32_t a[10];
        load_own_row_bf16(a, s_rows[w], row);

        uint32_t gsum[NDIM];
        gram_sweep_bf16(a, s_rows[w], gsum);

        // weighted target pairs, absolute-pair triangle layout (bf16x2):
        //   pair q of row i covers (2q, 2q+1); weights: j<i ->0, j==i ->1, j>i ->2
        if (lane < NDIM) {
            const int i  = lane;
            const int qi = i >> 1;
            uint32_t* gd = &s_g[w][trow(i) - qi];
            #pragma unroll
            for (int q = 0; q < 10; q++) {
                if (q >= qi) {
                    uint32_t pair = prmt(gsum[2 * q], gsum[2 * q + 1], 0x5410u);
                    uint32_t wsel = (q > qi) ? 0x40004000u                      // {2,2}
                                  : ((i & 1) == 0 ? 0x40003F80u                 // {1,2}
                                                  : 0x3F800000u);               // {0,1}
                    gd[q] = hmul2(pair, wsel);
                }
            }
        }
        __syncwarp();

        // batched gathers: all 44 loads issued with full unroll -> MLP covers L2 latency once
        uint32_t pacc[NMATS];
        {
            const uint32_t g0 = s_g[w][lane];
            const uint32_t g1 = s_g[w][lane + 32];
            const uint32_t g2 = s_g[w][lane + 64];
            const uint32_t g3 = (lane + 96 < TPAIRS) ? s_g[w][lane + 96] : 0u;
            #pragma unroll
            for (int r = 0; r < NMATS; r++) {
                const uint32_t* hp = g_hfeat + (size_t)s_wi[w][1 + r] * TSTRIDE;
                uint32_t v0 = hp[lane];
                uint32_t v1 = hp[lane + 32];
                uint32_t v2 = hp[lane + 64];
                uint32_t v3 = (lane + 96 < TPAIRS) ? hp[lane + 96] : 0u;
                uint32_t p = 0;
                p = hfma2(v0, g0, p);
                p = hfma2(v1, g1, p);
                p = hfma2(v2, g2, p);
                p = hfma2(v3, g3, p);
                pacc[r] = p;
            }
        }

        float loss = 0.0f;
        #pragma unroll
        for (int r = 0; r < NMATS; r++) {
            uint32_t p = pacc[r];
            #pragma unroll
            for (int d = 16; d; d >>= 1)
                p = hadd2(p, __shfl_xor_sync(0xffffffffu, p, d));
            uint32_t tsum = hadd2(p, prmt(p, p, 0x1032u));
            float part = __uint_as_float(tsum << 16);
            loss += (r == 0) ? softplusf(-part) : softplusf(part);
        }

        if (lane == 0) g_partials[b] = loss;
    }
    __syncthreads();

    if (threadIdx.x == 0) {
        __threadfence();
        unsigned old = atomicAdd(&g_ctr, 1u);
        s_last = (old % (unsigned)gridDim.x == (unsigned)gridDim.x - 1u) ? 1u : 0u;
    }
    __syncthreads();

    // last arriving block: deterministic fixed-order mean
    if (s_last) {
        __shared__ float s_red[256];
        const int t = threadIdx.x;
        float acc = 0.0f;
        const int n4 = B >> 2;
        const float4* p = (const float4*)g_partials;
        for (int i = t; i < n4; i += 256) {
            float4 v = p[i];
            acc += (v.x + v.y) + (v.z + v.w);
        }
        s_red[t] = acc;
        __syncthreads();
        #pragma unroll
        for (int ww = 128; ww > 0; ww >>= 1) {
            if (t < ww) s_red[t] += s_red[t + ww];
            __syncthreads();
        }
        if (t == 0) out[0] = s_red[0] / (float)B;
    }
}

extern "C" void kernel_launch(void* const* d_in, const int* in_sizes, int n_in,
                              void* d_out, int out_size)
{
    const float* Wt   = (const float*)d_in[0];
    const float* Wc   = (const float*)d_in[1];
    const int*   tidx = (const int*)d_in[2];
    const int*   cidx = (const int*)d_in[3];
    const int*   nidx = (const int*)d_in[4];

    int vocab = in_sizes[1] / 400;
    int B = in_sizes[2];
    if (B > BMAX) B = BMAX;
    int kneg = in_sizes[4] / (B > 0 ? B : 1);

    w2dm_hgram<<<(vocab + 7) / 8, 256>>>(Wc, vocab);
    w2dm_main<<<(B + 7) / 8, 256>>>(Wt, tidx, cidx, nidx, kneg, B, (float*)d_out);
}

// round 11
// speedup vs baseline: 2.6902x; 1.0531x over previous
#include <cuda_runtime.h>
#include <cstdint>

// Word2DM via Gram features:
//   sim(b,r) = ||Bt^T X||_F^2 = <Bt Bt^T, X X^T>  (row-Gram matrices, 20x20)
// K0: mark referenced context words (byte flags; replay-safe idempotent writes).
// K1: bf16 Gram sweep -> triangle bf16 features, ONLY for referenced words.
// K2: per sample: target Gram + 11 batched triangle dots; product-form softplus;
//     fused last-block fixed-order mean.

#define NDIM      20
#define NMATS     11
#define BMAX      32768
#define VOCAB_MAX 100000
#define TPAIRS    110          // padded-triangle u32 pairs per word
#define TSTRIDE   112          // u32 stride per word (16B aligned)

__device__ float    g_partials[BMAX];
__device__ uint32_t g_hfeat[(size_t)VOCAB_MAX * TSTRIDE];   // 44.8 MB
__device__ unsigned char g_flags[VOCAB_MAX];                 // referenced-word marks
__device__ unsigned int g_ctr;                               // replay-safe modulo counter

typedef unsigned long long ull;

static __device__ __forceinline__ uint32_t hfma2(uint32_t a, uint32_t b, uint32_t c) {
    uint32_t d;
    asm("fma.rn.bf16x2 %0, %1, %2, %3;" : "=r"(d) : "r"(a), "r"(b), "r"(c));
    return d;
}
static __device__ __forceinline__ uint32_t hadd2(uint32_t a, uint32_t b) {
    uint32_t d;
    asm("add.bf16x2 %0, %1, %2;" : "=r"(d) : "r"(a), "r"(b));
    return d;
}
static __device__ __forceinline__ uint32_t hmul2(uint32_t a, uint32_t b) {
    uint32_t d;
    asm("mul.bf16x2 %0, %1, %2;" : "=r"(d) : "r"(a), "r"(b));
    return d;
}
static __device__ __forceinline__ uint32_t prmt(uint32_t a, uint32_t b, uint32_t sel) {
    uint32_t d;
    asm("prmt.b32 %0, %1, %2, %3;" : "=r"(d) : "r"(a), "r"(b), "r"(sel));
    return d;
}
static __device__ __forceinline__ ull packu2(uint32_t lo, uint32_t hi) {
    ull r;
    asm("mov.b64 %0, {%1, %2};" : "=l"(r) : "r"(lo), "r"(hi));
    return r;
}
static __device__ __forceinline__ uint32_t bf2(float hi, float lo) {
    uint32_t r;
    asm("cvt.rn.bf16x2.f32 %0, %1, %2;" : "=r"(r) : "f"(hi), "f"(lo));
    return r;
}

// triangle row start (u32 units): R(2t)=t*(21-t), R(2t+1)=20t+10-t*t
static __device__ __forceinline__ int trow(int i) {
    int t = i >> 1;
    return (i & 1) ? (20 * t + 10 - t * t) : (t * (21 - t));
}

// stage one word (400 f32, streamed/evict-first) -> bf16 rows, 48B row stride
static __device__ __forceinline__ void stage_bf16(uint16_t* __restrict__ dst16,
                                                  const float* __restrict__ src,
                                                  int lane)
{
    const float4* s = (const float4*)src;
    #pragma unroll
    for (int k = 0; k < 4; k++) {
        int f = lane + 32 * k;
        if (f < 100) {
            float4 v = __ldcs(s + f);               // evict-first: protect L2 table
            int row = f / 5, q = f % 5;
            uint32_t lo = bf2(v.y, v.x);
            uint32_t hi = bf2(v.w, v.z);
            *(ull*)(dst16 + row * 24 + q * 4) = packu2(lo, hi);
        }
    }
}

// bf16 Gram sweep: lane's row in a[10] (bf16x2), rows at base16 (48B stride).
// gsum[j]: bf16x2 with BOTH halves = dot(row_lane, row_j).
static __device__ __forceinline__ void gram_sweep_bf16(const uint32_t* __restrict__ a,
                                                       const uint16_t* __restrict__ base16,
                                                       uint32_t* __restrict__ gsum)
{
    #pragma unroll
    for (int j = 0; j < NDIM; j++) {
        const uint16_t* rj = base16 + j * 24;
        uint4 b0 = *(const uint4*)rj;
        uint4 b1 = *(const uint4*)(rj + 8);
        uint2 b2 = *(const uint2*)(rj + 16);
        uint32_t p0 = 0, p1 = 0;
        p0 = hfma2(a[0], b0.x, p0);  p1 = hfma2(a[1], b0.y, p1);
        p0 = hfma2(a[2], b0.z, p0);  p1 = hfma2(a[3], b0.w, p1);
        p0 = hfma2(a[4], b1.x, p0);  p1 = hfma2(a[5], b1.y, p1);
        p0 = hfma2(a[6], b1.z, p0);  p1 = hfma2(a[7], b1.w, p1);
        p0 = hfma2(a[8], b2.x, p0);  p1 = hfma2(a[9], b2.y, p1);
        uint32_t v = hadd2(p0, p1);
        gsum[j] = hadd2(v, prmt(v, v, 0x1032u));    // halves-sum in both halves
    }
}

static __device__ __forceinline__ void load_own_row_bf16(uint32_t* __restrict__ a,
                                                         const uint16_t* __restrict__ base16,
                                                         int row)
{
    const uint16_t* r = base16 + row * 24;
    uint4 m0 = *(const uint4*)r;
    uint4 m1 = *(const uint4*)(r + 8);
    uint2 m2 = *(const uint2*)(r + 16);
    a[0] = m0.x; a[1] = m0.y; a[2] = m0.z; a[3] = m0.w;
    a[4] = m1.x; a[5] = m1.y; a[6] = m1.z; a[7] = m1.w;
    a[8] = m2.x; a[9] = m2.y;
}

// ── K0: mark referenced context words (idempotent -> graph-replay safe) ──
__global__ __launch_bounds__(256)
void w2dm_mark(const int* __restrict__ cidx, const int* __restrict__ nidx,
               int B, int kneg)
{
    int t = blockIdx.x * 256 + threadIdx.x;
    int total = B * (1 + kneg);
    if (t < total) {
        int v = (t < B) ? cidx[t] : nidx[t - B];
        g_flags[v] = 1;
    }
}

// ── K1: triangle Gram features for REFERENCED vocab words of W_context ──
__global__ __launch_bounds__(256)
void w2dm_hgram(const float* __restrict__ Wc, int vocab)
{
    __shared__ __align__(16) uint16_t s_rows[8][480];
    const int w    = threadIdx.x >> 5;
    const int lane = threadIdx.x & 31;
    const int word = blockIdx.x * 8 + w;
    if (word >= vocab || word >= VOCAB_MAX) return;
    if (!g_flags[word]) return;              // unreferenced: features never read

    stage_bf16(s_rows[w], Wc + (size_t)word * 400, lane);
    __syncwarp();

    const int row = (lane < NDIM) ? lane : 0;
    uint32_t a[10];
    load_own_row_bf16(a, s_rows[w], row);

    uint32_t gsum[NDIM];
    gram_sweep_bf16(a, s_rows[w], gsum);

    if (lane < NDIM) {
        const int qi = lane >> 1;
        uint32_t* out = g_hfeat + (size_t)word * TSTRIDE + trow(lane) - qi;
        #pragma unroll
        for (int q = 0; q < 10; q++)
            if (q >= qi)
                out[q] = prmt(gsum[2 * q], gsum[2 * q + 1], 0x5410u);  // {lo=g2q, hi=g2q+1}
    }
}

// ── K2: per-sample target Gram + 11 batched triangle dots -> loss; fused mean ──
__global__ __launch_bounds__(256)
void w2dm_main(const float* __restrict__ Wt,
               const int*   __restrict__ tidx,
               const int*   __restrict__ cidx,
               const int*   __restrict__ nidx,
               int kneg, int B, float* __restrict__ out)
{
    __shared__ __align__(16) uint16_t s_rows[8][480];
    __shared__ __align__(16) uint32_t s_g[8][TSTRIDE];   // weighted target pairs (bf16x2)
    __shared__ int s_wi[8][12];
    __shared__ unsigned s_last;

    const int w    = threadIdx.x >> 5;
    const int lane = threadIdx.x & 31;
    const int b    = blockIdx.x * 8 + w;

    if (b < B) {
        if (lane < 12) {
            int v;
            if (lane == 0)      v = tidx[b];
            else if (lane == 1) v = cidx[b];
            else                v = nidx[b * kneg + (lane - 2)];
            s_wi[w][lane] = v;
        }
        __syncwarp();

        stage_bf16(s_rows[w], Wt + (size_t)s_wi[w][0] * 400, lane);
        __syncwarp();

        const int row = (lane < NDIM) ? lane : 0;
        uint32_t a[10];
        load_own_row_bf16(a, s_rows[w], row);

        uint32_t gsum[NDIM];
        gram_sweep_bf16(a, s_rows[w], gsum);

        // weighted target pairs, absolute-pair triangle layout (bf16x2):
        //   pair q of row i covers (2q, 2q+1); weights: j<i ->0, j==i ->1, j>i ->2
        if (lane < NDIM) {
            const int i  = lane;
            const int qi = i >> 1;
            uint32_t* gd = &s_g[w][trow(i) - qi];
            #pragma unroll
            for (int q = 0; q < 10; q++) {
                if (q >= qi) {
                    uint32_t pair = prmt(gsum[2 * q], gsum[2 * q + 1], 0x5410u);
                    uint32_t wsel = (q > qi) ? 0x40004000u                      // {2,2}
                                  : ((i & 1) == 0 ? 0x40003F80u                 // {1,2}
                                                  : 0x3F800000u);               // {0,1}
                    gd[q] = hmul2(pair, wsel);
                }
            }
        }
        __syncwarp();

        // batched gathers: all 44 loads issued together -> MLP covers L2 latency once
        uint32_t pacc[NMATS];
        {
            const uint32_t g0 = s_g[w][lane];
            const uint32_t g1 = s_g[w][lane + 32];
            const uint32_t g2 = s_g[w][lane + 64];
            const uint32_t g3 = (lane + 96 < TPAIRS) ? s_g[w][lane + 96] : 0u;
            #pragma unroll
            for (int r = 0; r < NMATS; r++) {
                const uint32_t* hp = g_hfeat + (size_t)s_wi[w][1 + r] * TSTRIDE;
                uint32_t v0 = hp[lane];
                uint32_t v1 = hp[lane + 32];
                uint32_t v2 = hp[lane + 64];
                uint32_t v3 = (lane + 96 < TPAIRS) ? hp[lane + 96] : 0u;
                uint32_t p = 0;
                p = hfma2(v0, g0, p);
                p = hfma2(v1, g1, p);
                p = hfma2(v2, g2, p);
                p = hfma2(v3, g3, p);
                pacc[r] = p;
            }
        }

        // product-form loss: loss = log( prod_r (1 + e^{y_r}) ),
        // y_0 = -sim_ctx, y_r = +sim_r.  (sims ~1e-9 -> no overflow risk)
        float prod = 1.0f;
        #pragma unroll
        for (int r = 0; r < NMATS; r++) {
            uint32_t p = pacc[r];
            #pragma unroll
            for (int d = 16; d; d >>= 1)
                p = hadd2(p, __shfl_xor_sync(0xffffffffu, p, d));
            uint32_t tsum = hadd2(p, prmt(p, p, 0x1032u));
            float sim = __uint_as_float(tsum << 16);
            float y = (r == 0) ? -sim : sim;
            prod *= 1.0f + __expf(y);
        }
        float loss = __logf(prod);

        if (lane == 0) g_partials[b] = loss;
    }
    __syncthreads();

    if (threadIdx.x == 0) {
        __threadfence();
        unsigned old = atomicAdd(&g_ctr, 1u);
        s_last = (old % (unsigned)gridDim.x == (unsigned)gridDim.x - 1u) ? 1u : 0u;
    }
    __syncthreads();

    // last arriving block: deterministic fixed-order mean
    if (s_last) {
        __shared__ float s_red[256];
        const int t = threadIdx.x;
        float acc = 0.0f;
        const int n4 = B >> 2;
        const float4* p = (const float4*)g_partials;
        for (int i = t; i < n4; i += 256) {
            float4 v = p[i];
            acc += (v.x + v.y) + (v.z + v.w);
        }
        s_red[t] = acc;
        __syncthreads();
        #pragma unroll
        for (int ww = 128; ww > 0; ww >>= 1) {
            if (t < ww) s_red[t] += s_red[t + ww];
            __syncthreads();
        }
        if (t == 0) out[0] = s_red[0] / (float)B;
    }
}

extern "C" void kernel_launch(void* const* d_in, const int* in_sizes, int n_in,
                              void* d_out, int out_size)
{
    const float* Wt   = (const float*)d_in[0];
    const float* Wc   = (const float*)d_in[1];
    const int*   tidx = (const int*)d_in[2];
    const int*   cidx = (const int*)d_in[3];
    const int*   nidx = (const int*)d_in[4];

    int vocab = in_sizes[1] / 400;
    int B = in_sizes[2];
    if (B > BMAX) B = BMAX;
    int kneg = in_sizes[4] / (B > 0 ? B : 1);

    int marks = B * (1 + kneg);
    w2dm_mark<<<(marks + 255) / 256, 256>>>(cidx, nidx, B, kneg);
    w2dm_hgram<<<(vocab + 7) / 8, 256>>>(Wc, vocab);
    w2dm_main<<<(B + 7) / 8, 256>>>(Wt, tidx, cidx, nidx, kneg, B, (float*)d_out);
}

// round 12
// speedup vs baseline: 3.3269x; 1.2367x over previous
#include <cuda_runtime.h>
#include <cstdint>

// Word2DM via Gram features, Gram computed by per-warp HMMA (mma.sync bf16):
//   sim(b,r) = <Bt Bt^T, X X^T>, Gram G = A A^T with A = 20x20 word matrix.
// Identity used: for mma.m16n8k16.row.col, the B-fragment of A^T equals the
// non-trans ldmatrix output on A's rows -> 4 ldmatrix.x4 serve both operands.
// K0: mark referenced context words. K1: triangle bf16 features (referenced).
// K2: per-sample target Gram (HMMA) + 11 batched triangle dots; product-form
//     softplus; fused last-block fixed-order mean.

#define NDIM      20
#define NMATS     11
#define BMAX      32768
#define VOCAB_MAX 100000
#define TPAIRS    110          // triangle u32 pairs per word
#define TSTRIDE   112          // u32 stride per word (16B aligned)

__device__ float    g_partials[BMAX];
__device__ uint32_t g_hfeat[(size_t)VOCAB_MAX * TSTRIDE];   // 44.8 MB
__device__ unsigned char g_flags[VOCAB_MAX];
__device__ unsigned int g_ctr;                               // replay-safe modulo counter

typedef unsigned long long ull;

static __device__ __forceinline__ uint32_t hfma2(uint32_t a, uint32_t b, uint32_t c) {
    uint32_t d;
    asm("fma.rn.bf16x2 %0, %1, %2, %3;" : "=r"(d) : "r"(a), "r"(b), "r"(c));
    return d;
}
static __device__ __forceinline__ uint32_t hadd2(uint32_t a, uint32_t b) {
    uint32_t d;
    asm("add.bf16x2 %0, %1, %2;" : "=r"(d) : "r"(a), "r"(b));
    return d;
}
static __device__ __forceinline__ uint32_t hmul2(uint32_t a, uint32_t b) {
    uint32_t d;
    asm("mul.bf16x2 %0, %1, %2;" : "=r"(d) : "r"(a), "r"(b));
    return d;
}
static __device__ __forceinline__ uint32_t prmt(uint32_t a, uint32_t b, uint32_t sel) {
    uint32_t d;
    asm("prmt.b32 %0, %1, %2, %3;" : "=r"(d) : "r"(a), "r"(b), "r"(sel));
    return d;
}
static __device__ __forceinline__ ull packu2(uint32_t lo, uint32_t hi) {
    ull r;
    asm("mov.b64 %0, {%1, %2};" : "=l"(r) : "r"(lo), "r"(hi));
    return r;
}
static __device__ __forceinline__ uint32_t bf2(float hi, float lo) {
    uint32_t r;
    asm("cvt.rn.bf16x2.f32 %0, %1, %2;" : "=r"(r) : "f"(hi), "f"(lo));
    return r;
}
static __device__ __forceinline__ uint32_t smem_u32(const void* p) {
    uint32_t a;
    asm("{ .reg .u64 t; cvta.to.shared.u64 t, %1; cvt.u32.u64 %0, t; }" : "=r"(a) : "l"(p));
    return a;
}
static __device__ __forceinline__ void ldsm_x4(uint32_t& r0, uint32_t& r1,
                                               uint32_t& r2, uint32_t& r3, uint32_t addr) {
    asm volatile("ldmatrix.sync.aligned.m8n8.x4.shared.b16 {%0,%1,%2,%3}, [%4];"
                 : "=r"(r0), "=r"(r1), "=r"(r2), "=r"(r3) : "r"(addr));
}
static __device__ __forceinline__ void mma_bf16(float& d0, float& d1, float& d2, float& d3,
                                                uint32_t a0, uint32_t a1, uint32_t a2, uint32_t a3,
                                                uint32_t b0, uint32_t b1,
                                                float c0, float c1, float c2, float c3) {
    asm volatile("mma.sync.aligned.m16n8k16.row.col.f32.bf16.bf16.f32 "
                 "{%0,%1,%2,%3}, {%4,%5,%6,%7}, {%8,%9}, {%10,%11,%12,%13};"
                 : "=f"(d0), "=f"(d1), "=f"(d2), "=f"(d3)
                 : "r"(a0), "r"(a1), "r"(a2), "r"(a3), "r"(b0), "r"(b1),
                   "f"(c0), "f"(c1), "f"(c2), "f"(c3));
}

// triangle row start (u32 units): R(2t)=t*(21-t), R(2t+1)=20t+10-t*t
static __device__ __forceinline__ int trow(int i) {
    int t = i >> 1;
    return (i & 1) ? (20 * t + 10 - t * t) : (t * (21 - t));
}

// zero the 32x32 bf16 word tile (2048B), 64B row stride
static __device__ __forceinline__ void zero_tile(uint16_t* dst16, int lane) {
    uint4 z = make_uint4(0, 0, 0, 0);
    #pragma unroll
    for (int k = 0; k < 4; k++)
        *(uint4*)(dst16 + (lane + 32 * k) * 8) = z;
}

// stage one word (400 f32, evict-first) -> bf16 rows at 64B stride (cols 20-31 stay 0)
static __device__ __forceinline__ void stage_bf16(uint16_t* __restrict__ dst16,
                                                  const float* __restrict__ src,
                                                  int lane)
{
    const float4* s = (const float4*)src;
    #pragma unroll
    for (int k = 0; k < 4; k++) {
        int f = lane + 32 * k;
        if (f < 100) {
            float4 v = __ldcs(s + f);
            int row = f / 5, q = f % 5;
            *(ull*)(dst16 + row * 32 + q * 4) = packu2(bf2(v.y, v.x), bf2(v.w, v.z));
        }
    }
}

// Per-warp Gram via HMMA. Input: 32x32 bf16 tile in smem (64B stride, padded w/ 0).
// Output: 4 D tiles (f32), d[t][0..3]; tile t covers (M0,N0) in TILE_M0/TILE_N0.
__device__ __constant__ const int TILE_M0_[4] = {0, 0, 0, 16};
__device__ __constant__ const int TILE_N0_[4] = {0, 8, 16, 16};

static __device__ __forceinline__ void gram_hmma(uint32_t sb, int lane, float d[4][4]) {
    const int r = lane & 7, g = lane >> 3;
    // x4 lane-address: tiles (rows 0-7), (rows 8-15), (rows 0-7,+16B), (rows 8-15,+16B)
    uint32_t adr = sb + (uint32_t)((r + ((g & 1) ? 8 : 0)) * 64 + ((g >> 1) ? 16 : 0));
    uint32_t X00[4], X01[4], X10[4], X11[4];
    ldsm_x4(X00[0], X00[1], X00[2], X00[3], adr);           // rows 0-15,  k 0-15
    ldsm_x4(X01[0], X01[1], X01[2], X01[3], adr + 32);      // rows 0-15,  k 16-31
    ldsm_x4(X10[0], X10[1], X10[2], X10[3], adr + 1024);    // rows 16-31, k 0-15
    ldsm_x4(X11[0], X11[1], X11[2], X11[3], adr + 1024 + 32);

    #pragma unroll
    for (int t = 0; t < 4; t++) d[t][0] = d[t][1] = d[t][2] = d[t][3] = 0.0f;

    // B frag (n-block, k-block) = {X.r0, X.r2} for n=rows 0-7 of X, {X.r1, X.r3} for rows 8-15
    // T0: m0-15 x n0-7
    mma_bf16(d[0][0], d[0][1], d[0][2], d[0][3], X00[0], X00[1], X00[2], X00[3],
             X00[0], X00[2], d[0][0], d[0][1], d[0][2], d[0][3]);
    mma_bf16(d[0][0], d[0][1], d[0][2], d[0][3], X01[0], X01[1], X01[2], X01[3],
             X01[0], X01[2], d[0][0], d[0][1], d[0][2], d[0][3]);
    // T1: m0-15 x n8-15
    mma_bf16(d[1][0], d[1][1], d[1][2], d[1][3], X00[0], X00[1], X00[2], X00[3],
             X00[1], X00[3], d[1][0], d[1][1], d[1][2], d[1][3]);
    mma_bf16(d[1][0], d[1][1], d[1][2], d[1][3], X01[0], X01[1], X01[2], X01[3],
             X01[1], X01[3], d[1][0], d[1][1], d[1][2], d[1][3]);
    // T2: m0-15 x n16-23
    mma_bf16(d[2][0], d[2][1], d[2][2], d[2][3], X00[0], X00[1], X00[2], X00[3],
             X10[0], X10[2], d[2][0], d[2][1], d[2][2], d[2][3]);
    mma_bf16(d[2][0], d[2][1], d[2][2], d[2][3], X01[0], X01[1], X01[2], X01[3],
             X11[0], X11[2], d[2][0], d[2][1], d[2][2], d[2][3]);
    // T3: m16-31 x n16-23
    mma_bf16(d[3][0], d[3][1], d[3][2], d[3][3], X10[0], X10[1], X10[2], X10[3],
             X10[0], X10[2], d[3][0], d[3][1], d[3][2], d[3][3]);
    mma_bf16(d[3][0], d[3][1], d[3][2], d[3][3], X11[0], X11[1], X11[2], X11[3],
             X11[0], X11[2], d[3][0], d[3][1], d[3][2], d[3][3]);
}

// ── K0: mark referenced context words (idempotent -> graph-replay safe) ──
__global__ __launch_bounds__(256)
void w2dm_mark(const int* __restrict__ cidx, const int* __restrict__ nidx,
               int B, int kneg)
{
    int t = blockIdx.x * 256 + threadIdx.x;
    int total = B * (1 + kneg);
    if (t < total) {
        int v = (t < B) ? cidx[t] : nidx[t - B];
        g_flags[v] = 1;
    }
}

// ── K1: triangle Gram features for REFERENCED vocab words of W_context ──
__global__ __launch_bounds__(256)
void w2dm_hgram(const float* __restrict__ Wc, int vocab)
{
    __shared__ __align__(16) uint16_t s_rows[8][1024];   // 32x32 bf16, 64B stride
    const int w    = threadIdx.x >> 5;
    const int lane = threadIdx.x & 31;
    const int word = blockIdx.x * 8 + w;
    if (word >= vocab || word >= VOCAB_MAX) return;
    if (!g_flags[word]) return;

    zero_tile(s_rows[w], lane);
    __syncwarp();
    stage_bf16(s_rows[w], Wc + (size_t)word * 400, lane);
    __syncwarp();

    float d[4][4];
    gram_hmma(smem_u32(s_rows[w]), lane, d);

    uint32_t* out = g_hfeat + (size_t)word * TSTRIDE;
    const int lr = lane >> 2, lc = lane & 3;
    #pragma unroll
    for (int t = 0; t < 4; t++) {
        const int i0 = TILE_M0_[t] + lr;
        const int p  = (TILE_N0_[t] >> 1) + lc;
        const int i1 = i0 + 8;
        if (p < 10) {
            if (i0 < 20 && p >= (i0 >> 1))
                out[trow(i0) - (i0 >> 1) + p] = bf2(d[t][1], d[t][0]);
            if (i1 < 20 && p >= (i1 >> 1))
                out[trow(i1) - (i1 >> 1) + p] = bf2(d[t][3], d[t][2]);
        }
    }
}

// ── K2: per-sample target Gram (HMMA) + 11 batched triangle dots; fused mean ──
__global__ __launch_bounds__(256)
void w2dm_main(const float* __restrict__ Wt,
               const int*   __restrict__ tidx,
               const int*   __restrict__ cidx,
               const int*   __restrict__ nidx,
               int kneg, int B, float* __restrict__ out)
{
    __shared__ __align__(16) uint16_t s_rows[8][1024];
    __shared__ __align__(16) uint32_t s_g[8][TSTRIDE];   // weighted target pairs (bf16x2)
    __shared__ int s_wi[8][12];
    __shared__ unsigned s_last;

    const int w    = threadIdx.x >> 5;
    const int lane = threadIdx.x & 31;
    const int b    = blockIdx.x * 8 + w;

    if (b < B) {
        if (lane < 12) {
            int v;
            if (lane == 0)      v = tidx[b];
            else if (lane == 1) v = cidx[b];
            else                v = nidx[b * kneg + (lane - 2)];
            s_wi[w][lane] = v;
        }
        __syncwarp();

        zero_tile(s_rows[w], lane);
        __syncwarp();
        stage_bf16(s_rows[w], Wt + (size_t)s_wi[w][0] * 400, lane);
        __syncwarp();

        float d[4][4];
        gram_hmma(smem_u32(s_rows[w]), lane, d);

        // weighted triangle scratch: pair p of row i covers cols (2p, 2p+1);
        // weights: col<i ->0, col==i ->1, col>i ->2
        const int lr = lane >> 2, lc = lane & 3;
        #pragma unroll
        for (int t = 0; t < 4; t++) {
            const int p = (TILE_N0_[t] >> 1) + lc;
            if (p < 10) {
                #pragma unroll
                for (int h = 0; h < 2; h++) {
                    const int i  = TILE_M0_[t] + lr + 8 * h;
                    const int qi = i >> 1;
                    if (i < 20 && p >= qi) {
                        uint32_t pair = bf2(d[t][2 * h + 1], d[t][2 * h]);
                        uint32_t wsel = (p > qi) ? 0x40004000u
                                      : ((i & 1) == 0 ? 0x40003F80u : 0x3F800000u);
                        s_g[w][trow(i) - qi + p] = hmul2(pair, wsel);
                    }
                }
            }
        }
        __syncwarp();

        // batched gathers: all 44 loads issued together -> MLP covers L2 latency once
        uint32_t pacc[NMATS];
        {
            const uint32_t g0 = s_g[w][lane];
            const uint32_t g1 = s_g[w][lane + 32];
            const uint32_t g2 = s_g[w][lane + 64];
            const uint32_t g3 = (lane + 96 < TPAIRS) ? s_g[w][lane + 96] : 0u;
            #pragma unroll
            for (int r = 0; r < NMATS; r++) {
                const uint32_t* hp = g_hfeat + (size_t)s_wi[w][1 + r] * TSTRIDE;
                uint32_t v0 = hp[lane];
                uint32_t v1 = hp[lane + 32];
                uint32_t v2 = hp[lane + 64];
                uint32_t v3 = (lane + 96 < TPAIRS) ? hp[lane + 96] : 0u;
                uint32_t p = 0;
                p = hfma2(v0, g0, p);
                p = hfma2(v1, g1, p);
                p = hfma2(v2, g2, p);
                p = hfma2(v3, g3, p);
                pacc[r] = p;
            }
        }

        // product-form loss: log( prod_r (1 + e^{y_r}) ), sims ~1e-9 -> safe
        float prod = 1.0f;
        #pragma unroll
        for (int r = 0; r < NMATS; r++) {
            uint32_t p = pacc[r];
            #pragma unroll
            for (int dd = 16; dd; dd >>= 1)
                p = hadd2(p, __shfl_xor_sync(0xffffffffu, p, dd));
            uint32_t tsum = hadd2(p, prmt(p, p, 0x1032u));
            float sim = __uint_as_float(tsum << 16);
            float y = (r == 0) ? -sim : sim;
            prod *= 1.0f + __expf(y);
        }
        float loss = __logf(prod);

        if (lane == 0) g_partials[b] = loss;
    }
    __syncthreads();

    if (threadIdx.x == 0) {
        __threadfence();
        unsigned old = atomicAdd(&g_ctr, 1u);
        s_last = (old % (unsigned)gridDim.x == (unsigned)gridDim.x - 1u) ? 1u : 0u;
    }
    __syncthreads();

    if (s_last) {
        __shared__ float s_red[256];
        const int t = threadIdx.x;
        float acc = 0.0f;
        const int n4 = B >> 2;
        const float4* p = (const float4*)g_partials;
        for (int i = t; i < n4; i += 256) {
            float4 v = p[i];
            acc += (v.x + v.y) + (v.z + v.w);
        }
        s_red[t] = acc;
        __syncthreads();
        #pragma unroll
        for (int ww = 128; ww > 0; ww >>= 1) {
            if (t < ww) s_red[t] += s_red[t + ww];
            __syncthreads();
        }
        if (t == 0) out[0] = s_red[0] / (float)B;
    }
}

extern "C" void kernel_launch(void* const* d_in, const int* in_sizes, int n_in,
                              void* d_out, int out_size)
{
    const float* Wt   = (const float*)d_in[0];
    const float* Wc   = (const float*)d_in[1];
    const int*   tidx = (const int*)d_in[2];
    const int*   cidx = (const int*)d_in[3];
    const int*   nidx = (const int*)d_in[4];

    int vocab = in_sizes[1] / 400;
    int B = in_sizes[2];
    if (B > BMAX) B = BMAX;
    int kneg = in_sizes[4] / (B > 0 ? B : 1);

    int marks = B * (1 + kneg);
    w2dm_mark<<<(marks + 255) / 256, 256>>>(cidx, nidx, B, kneg);
    w2dm_hgram<<<(vocab + 7) / 8, 256>>>(Wc, vocab);
    w2dm_main<<<(B + 7) / 8, 256>>>(Wt, tidx, cidx, nidx, kneg, B, (float*)d_out);
}

// round 13
// speedup vs baseline: 3.7780x; 1.1356x over previous
#include <cuda_runtime.h>
#include <cstdint>

// Word2DM, fully fused persistent kernel:
//   sim(b,r) = <Bt Bt^T, X X^T>  (20x20 row-Gram matrices)
// Phase 0: mark referenced context words (idempotent flags).
// Phase A: per-warp HMMA Gram -> triangle bf16 features for referenced words.
// Phase B: per-sample target Gram (HMMA) + 11 batched triangle dots,
//          product-form softplus; last-arriving block does fixed-order mean.
// Grid sized to guaranteed-resident blocks (occupancy query) -> spin barriers safe.

#define NDIM      20
#define NMATS     11
#define BMAX      32768
#define VOCAB_MAX 100000
#define TPAIRS    110          // triangle u32 pairs per word
#define TSTRIDE   112          // u32 stride per word (16B aligned)

__device__ float    g_partials[BMAX];
__device__ uint32_t g_hfeat[(size_t)VOCAB_MAX * TSTRIDE];   // 44.8 MB
__device__ unsigned char g_flags[VOCAB_MAX];
__device__ unsigned int g_bar;     // grid-barrier epochs (monotonic, replay-safe)
__device__ unsigned int g_ctr;     // last-block-reduce counter (modulo pattern)

typedef unsigned long long ull;

static __device__ __forceinline__ uint32_t hfma2(uint32_t a, uint32_t b, uint32_t c) {
    uint32_t d;
    asm("fma.rn.bf16x2 %0, %1, %2, %3;" : "=r"(d) : "r"(a), "r"(b), "r"(c));
    return d;
}
static __device__ __forceinline__ uint32_t hadd2(uint32_t a, uint32_t b) {
    uint32_t d;
    asm("add.bf16x2 %0, %1, %2;" : "=r"(d) : "r"(a), "r"(b));
    return d;
}
static __device__ __forceinline__ uint32_t hmul2(uint32_t a, uint32_t b) {
    uint32_t d;
    asm("mul.bf16x2 %0, %1, %2;" : "=r"(d) : "r"(a), "r"(b));
    return d;
}
static __device__ __forceinline__ uint32_t prmt(uint32_t a, uint32_t b, uint32_t sel) {
    uint32_t d;
    asm("prmt.b32 %0, %1, %2, %3;" : "=r"(d) : "r"(a), "r"(b), "r"(sel));
    return d;
}
static __device__ __forceinline__ ull packu2(uint32_t lo, uint32_t hi) {
    ull r;
    asm("mov.b64 %0, {%1, %2};" : "=l"(r) : "r"(lo), "r"(hi));
    return r;
}
static __device__ __forceinline__ uint32_t bf2(float hi, float lo) {
    uint32_t r;
    asm("cvt.rn.bf16x2.f32 %0, %1, %2;" : "=r"(r) : "f"(hi), "f"(lo));
    return r;
}
static __device__ __forceinline__ uint32_t smem_u32(const void* p) {
    uint32_t a;
    asm("{ .reg .u64 t; cvta.to.shared.u64 t, %1; cvt.u32.u64 %0, t; }" : "=r"(a) : "l"(p));
    return a;
}
static __device__ __forceinline__ void ldsm_x4(uint32_t& r0, uint32_t& r1,
                                               uint32_t& r2, uint32_t& r3, uint32_t addr) {
    asm volatile("ldmatrix.sync.aligned.m8n8.x4.shared.b16 {%0,%1,%2,%3}, [%4];"
                 : "=r"(r0), "=r"(r1), "=r"(r2), "=r"(r3) : "r"(addr));
}
static __device__ __forceinline__ void mma_bf16(float& d0, float& d1, float& d2, float& d3,
                                                uint32_t a0, uint32_t a1, uint32_t a2, uint32_t a3,
                                                uint32_t b0, uint32_t b1,
                                                float c0, float c1, float c2, float c3) {
    asm volatile("mma.sync.aligned.m16n8k16.row.col.f32.bf16.bf16.f32 "
                 "{%0,%1,%2,%3}, {%4,%5,%6,%7}, {%8,%9}, {%10,%11,%12,%13};"
                 : "=f"(d0), "=f"(d1), "=f"(d2), "=f"(d3)
                 : "r"(a0), "r"(a1), "r"(a2), "r"(a3), "r"(b0), "r"(b1),
                   "f"(c0), "f"(c1), "f"(c2), "f"(c3));
}

// epoch grid barrier: monotonic counter, two barriers per launch, replay-safe
static __device__ __forceinline__ void grid_barrier() {
    __syncthreads();
    if (threadIdx.x == 0) {
        __threadfence();
        unsigned o = atomicAdd(&g_bar, 1u);
        unsigned target = (o / gridDim.x + 1u) * gridDim.x;
        while ((int)(*(volatile unsigned*)&g_bar - target) < 0) { }
        __threadfence();
    }
    __syncthreads();
}

// triangle row start (u32 units): R(2t)=t*(21-t), R(2t+1)=20t+10-t*t
static __device__ __forceinline__ int trow(int i) {
    int t = i >> 1;
    return (i & 1) ? (20 * t + 10 - t * t) : (t * (21 - t));
}

// zero the 32x32 bf16 word tile (2048B), 64B row stride
static __device__ __forceinline__ void zero_tile(uint16_t* dst16, int lane) {
    uint4 z = make_uint4(0, 0, 0, 0);
    #pragma unroll
    for (int k = 0; k < 4; k++)
        *(uint4*)(dst16 + (lane + 32 * k) * 8) = z;
}

// stage one word (400 f32, evict-first) -> bf16 rows at 64B stride (pads stay 0)
static __device__ __forceinline__ void stage_bf16(uint16_t* __restrict__ dst16,
                                                  const float* __restrict__ src,
                                                  int lane)
{
    const float4* s = (const float4*)src;
    #pragma unroll
    for (int k = 0; k < 4; k++) {
        int f = lane + 32 * k;
        if (f < 100) {
            float4 v = __ldcs(s + f);
            int row = f / 5, q = f % 5;
            *(ull*)(dst16 + row * 32 + q * 4) = packu2(bf2(v.y, v.x), bf2(v.w, v.z));
        }
    }
}

// Per-warp Gram via HMMA. Input: 32x32 bf16 tile in smem (64B stride, zero-padded).
// Output: 4 D tiles (f32); tile t covers (M0,N0) in TILE_M0/TILE_N0.
__device__ __constant__ const int TILE_M0_[4] = {0, 0, 0, 16};
__device__ __constant__ const int TILE_N0_[4] = {0, 8, 16, 16};

static __device__ __forceinline__ void gram_hmma(uint32_t sb, int lane, float d[4][4]) {
    const int r = lane & 7, g = lane >> 3;
    uint32_t adr = sb + (uint32_t)((r + ((g & 1) ? 8 : 0)) * 64 + ((g >> 1) ? 16 : 0));
    uint32_t X00[4], X01[4], X10[4], X11[4];
    ldsm_x4(X00[0], X00[1], X00[2], X00[3], adr);           // rows 0-15,  k 0-15
    ldsm_x4(X01[0], X01[1], X01[2], X01[3], adr + 32);      // rows 0-15,  k 16-31
    ldsm_x4(X10[0], X10[1], X10[2], X10[3], adr + 1024);    // rows 16-31, k 0-15
    ldsm_x4(X11[0], X11[1], X11[2], X11[3], adr + 1024 + 32);

    #pragma unroll
    for (int t = 0; t < 4; t++) d[t][0] = d[t][1] = d[t][2] = d[t][3] = 0.0f;

    mma_bf16(d[0][0], d[0][1], d[0][2], d[0][3], X00[0], X00[1], X00[2], X00[3],
             X00[0], X00[2], d[0][0], d[0][1], d[0][2], d[0][3]);
    mma_bf16(d[0][0], d[0][1], d[0][2], d[0][3], X01[0], X01[1], X01[2], X01[3],
             X01[0], X01[2], d[0][0], d[0][1], d[0][2], d[0][3]);
    mma_bf16(d[1][0], d[1][1], d[1][2], d[1][3], X00[0], X00[1], X00[2], X00[3],
             X00[1], X00[3], d[1][0], d[1][1], d[1][2], d[1][3]);
    mma_bf16(d[1][0], d[1][1], d[1][2], d[1][3], X01[0], X01[1], X01[2], X01[3],
             X01[1], X01[3], d[1][0], d[1][1], d[1][2], d[1][3]);
    mma_bf16(d[2][0], d[2][1], d[2][2], d[2][3], X00[0], X00[1], X00[2], X00[3],
             X10[0], X10[2], d[2][0], d[2][1], d[2][2], d[2][3]);
    mma_bf16(d[2][0], d[2][1], d[2][2], d[2][3], X01[0], X01[1], X01[2], X01[3],
             X11[0], X11[2], d[2][0], d[2][1], d[2][2], d[2][3]);
    mma_bf16(d[3][0], d[3][1], d[3][2], d[3][3], X10[0], X10[1], X10[2], X10[3],
             X10[0], X10[2], d[3][0], d[3][1], d[3][2], d[3][3]);
    mma_bf16(d[3][0], d[3][1], d[3][2], d[3][3], X11[0], X11[1], X11[2], X11[3],
             X11[0], X11[2], d[3][0], d[3][1], d[3][2], d[3][3]);
}

__global__ __launch_bounds__(256)
void w2dm_all(const float* __restrict__ Wt,
              const float* __restrict__ Wc,
              const int*   __restrict__ tidx,
              const int*   __restrict__ cidx,
              const int*   __restrict__ nidx,
              int kneg, int B, int vocab, float* __restrict__ out)
{
    __shared__ __align__(16) uint16_t s_rows[8][1024];   // 32x32 bf16, 64B stride
    __shared__ __align__(16) uint32_t s_g[8][TSTRIDE];   // phase B scratch
    __shared__ int s_wi[8][12];
    __shared__ unsigned s_last;

    const int w    = threadIdx.x >> 5;
    const int lane = threadIdx.x & 31;
    const int warp_stride = gridDim.x * 8;

    // ── Phase 0: mark referenced context words (idempotent) ──
    {
        const int total = B * (1 + kneg);
        for (int t = blockIdx.x * 256 + threadIdx.x; t < total; t += gridDim.x * 256) {
            int v = (t < B) ? cidx[t] : nidx[t - B];
            g_flags[v] = 1;
        }
    }
    grid_barrier();

    // ── Phase A: triangle Gram features for referenced words ──
    zero_tile(s_rows[w], lane);      // padding (rows/cols >= 20) stays 0 across words
    __syncwarp();
    for (int word = blockIdx.x * 8 + w; word < vocab; word += warp_stride) {
        if (word < VOCAB_MAX && g_flags[word]) {
            stage_bf16(s_rows[w], Wc + (size_t)word * 400, lane);
            __syncwarp();

            float d[4][4];
            gram_hmma(smem_u32(s_rows[w]), lane, d);

            uint32_t* outp = g_hfeat + (size_t)word * TSTRIDE;
            const int lr = lane >> 2, lc = lane & 3;
            #pragma unroll
            for (int t = 0; t < 4; t++) {
                const int i0 = TILE_M0_[t] + lr;
                const int p  = (TILE_N0_[t] >> 1) + lc;
                const int i1 = i0 + 8;
                if (p < 10) {
                    if (i0 < 20 && p >= (i0 >> 1))
                        outp[trow(i0) - (i0 >> 1) + p] = bf2(d[t][1], d[t][0]);
                    if (i1 < 20 && p >= (i1 >> 1))
                        outp[trow(i1) - (i1 >> 1) + p] = bf2(d[t][3], d[t][2]);
                }
            }
            __syncwarp();
        }
    }
    grid_barrier();

    // ── Phase B: per-sample loss ──
    for (int b = blockIdx.x * 8 + w; b < B; b += warp_stride) {
        if (lane < 12) {
            int v;
            if (lane == 0)      v = tidx[b];
            else if (lane == 1) v = cidx[b];
            else                v = nidx[b * kneg + (lane - 2)];
            s_wi[w][lane] = v;
        }
        __syncwarp();

        stage_bf16(s_rows[w], Wt + (size_t)s_wi[w][0] * 400, lane);
        __syncwarp();

        float d[4][4];
        gram_hmma(smem_u32(s_rows[w]), lane, d);

        // weighted triangle scratch: pair p of row i covers cols (2p, 2p+1);
        // weights: col<i ->0, col==i ->1, col>i ->2
        const int lr = lane >> 2, lc = lane & 3;
        #pragma unroll
        for (int t = 0; t < 4; t++) {
            const int p = (TILE_N0_[t] >> 1) + lc;
            if (p < 10) {
                #pragma unroll
                for (int h = 0; h < 2; h++) {
                    const int i  = TILE_M0_[t] + lr + 8 * h;
                    const int qi = i >> 1;
                    if (i < 20 && p >= qi) {
                        uint32_t pair = bf2(d[t][2 * h + 1], d[t][2 * h]);
                        uint32_t wsel = (p > qi) ? 0x40004000u
                                      : ((i & 1) == 0 ? 0x40003F80u : 0x3F800000u);
                        s_g[w][trow(i) - qi + p] = hmul2(pair, wsel);
                    }
                }
            }
        }
        __syncwarp();

        // batched gathers: all 44 loads issued together -> one L2 latency
        uint32_t pacc[NMATS];
        {
            const uint32_t g0 = s_g[w][lane];
            const uint32_t g1 = s_g[w][lane + 32];
            const uint32_t g2 = s_g[w][lane + 64];
            const uint32_t g3 = (lane + 96 < TPAIRS) ? s_g[w][lane + 96] : 0u;
            #pragma unroll
            for (int r = 0; r < NMATS; r++) {
                const uint32_t* hp = g_hfeat + (size_t)s_wi[w][1 + r] * TSTRIDE;
                uint32_t v0 = hp[lane];
                uint32_t v1 = hp[lane + 32];
                uint32_t v2 = hp[lane + 64];
                uint32_t v3 = (lane + 96 < TPAIRS) ? hp[lane + 96] : 0u;
                uint32_t p = 0;
                p = hfma2(v0, g0, p);
                p = hfma2(v1, g1, p);
                p = hfma2(v2, g2, p);
                p = hfma2(v3, g3, p);
                pacc[r] = p;
            }
        }

        // product-form loss: log( prod_r (1 + e^{y_r}) ); sims ~1e-9 -> safe
        float prod = 1.0f;
        #pragma unroll
        for (int r = 0; r < NMATS; r++) {
            uint32_t p = pacc[r];
            #pragma unroll
            for (int dd = 16; dd; dd >>= 1)
                p = hadd2(p, __shfl_xor_sync(0xffffffffu, p, dd));
            uint32_t tsum = hadd2(p, prmt(p, p, 0x1032u));
            float sim = __uint_as_float(tsum << 16);
            float y = (r == 0) ? -sim : sim;
            prod *= 1.0f + __expf(y);
        }
        if (lane == 0) g_partials[b] = __logf(prod);
        __syncwarp();
    }
    __syncthreads();

    // last arriving block: deterministic fixed-order mean
    if (threadIdx.x == 0) {
        __threadfence();
        unsigned old = atomicAdd(&g_ctr, 1u);
        s_last = (old % (unsigned)gridDim.x == (unsigned)gridDim.x - 1u) ? 1u : 0u;
    }
    __syncthreads();

    if (s_last) {
        __shared__ float s_red[256];
        const int t = threadIdx.x;
        float acc = 0.0f;
        const int n4 = B >> 2;
        const float4* p = (const float4*)g_partials;
        for (int i = t; i < n4; i += 256) {
            float4 v = p[i];
            acc += (v.x + v.y) + (v.z + v.w);
        }
        s_red[t] = acc;
        __syncthreads();
        #pragma unroll
        for (int ww = 128; ww > 0; ww >>= 1) {
            if (t < ww) s_red[t] += s_red[t + ww];
            __syncthreads();
        }
        if (t == 0) out[0] = s_red[0] / (float)B;
    }
}

extern "C" void kernel_launch(void* const* d_in, const int* in_sizes, int n_in,
                              void* d_out, int out_size)
{
    const float* Wt   = (const float*)d_in[0];
    const float* Wc   = (const float*)d_in[1];
    const int*   tidx = (const int*)d_in[2];
    const int*   cidx = (const int*)d_in[3];
    const int*   nidx = (const int*)d_in[4];

    int vocab = in_sizes[1] / 400;
    int B = in_sizes[2];
    if (B > BMAX) B = BMAX;
    int kneg = in_sizes[4] / (B > 0 ? B : 1);

    // grid = guaranteed-resident blocks (spin barriers must not oversubscribe)
    int dev = 0;
    cudaGetDevice(&dev);
    int nsm = 0;
    cudaDeviceGetAttribute(&nsm, cudaDevAttrMultiProcessorCount, dev);
    if (nsm <= 0) nsm = 148;
    int maxb = 0;
    cudaOccupancyMaxActiveBlocksPerMultiprocessor(&maxb, w2dm_all, 256, 0);
    if (maxb < 1) maxb = 1;
    int grid = nsm * maxb;
    if (grid > 2048) grid = 2048;

    w2dm_all<<<grid, 256>>>(Wt, Wc, tidx, cidx, nidx, kneg, B, vocab, (float*)d_out);
}